// round 1
// baseline (speedup 1.0000x reference)
#include <cuda_runtime.h>
#include <math.h>

// Problem constants
#define BATCH 2
#define CCH   512
#define SEQ   4096          // 64*64 tokens
#define NH    8
#define HD    64            // head dim
#define BH    (BATCH*NH)    // 16

// Scratch (device globals: allocation-free)
__device__ float g_q[(size_t)BH * HD * SEQ];   // [bh][d][s]  (transposed for flash)
__device__ float g_k[(size_t)BH * HD * SEQ];   // [bh][d][s]
__device__ float g_v[(size_t)BH * SEQ * HD];   // [bh][s][d]
__device__ float g_o[(size_t)BATCH * SEQ * CCH]; // [b][s][c]  attention output (merged heads)

// ---------------------------------------------------------------------------
// Kernel 1: QKV projections.  tok[b,s,c] = x[b,c,s] (x gives k-major A tiles
// for free).  out = tok @ W^T + bias.  q,k stored [bh][d][s]; v stored [bh][s][d].
// Tile: 64(s) x 64(o) x 16(c), 256 threads, 4x4 register blocking.
// ---------------------------------------------------------------------------
__global__ __launch_bounds__(256) void qkv_kernel(
    const float* __restrict__ x,
    const float* __restrict__ Wq, const float* __restrict__ bq,
    const float* __restrict__ Wk, const float* __restrict__ bk,
    const float* __restrict__ Wv, const float* __restrict__ bv)
{
    __shared__ float As[16 * 64];   // [c][s]  k-major
    __shared__ float Bs[16 * 64];   // [c][o]  k-major

    const int t  = threadIdx.x;
    const int ty = t >> 4;          // 0..15  -> s rows
    const int tx = t & 15;          // 0..15  -> o cols
    const int s0 = blockIdx.x * 64;
    const int o0 = blockIdx.y * 64;
    const int z  = blockIdx.z;      // 0..5
    const int which = z % 3;        // 0=q,1=k,2=v
    const int b     = z / 3;

    const float* W;
    const float* bias;
    if (which == 0)      { W = Wq; bias = bq; }
    else if (which == 1) { W = Wk; bias = bk; }
    else                 { W = Wv; bias = bv; }

    const float4* xf4 = reinterpret_cast<const float4*>(x + (size_t)b * CCH * SEQ);
    const float4* Wf4 = reinterpret_cast<const float4*>(W);

    // staging maps
    const int ar  = t >> 4;   // c row for A (16 rows)
    const int ac4 = t & 15;   // float4 col (16 * 4 = 64 s)
    const int br  = t >> 2;   // o row for B (64 rows)
    const int bc4 = t & 3;    // float4 col (4 * 4 = 16 c)

    float acc[4][4];
#pragma unroll
    for (int i = 0; i < 4; i++)
#pragma unroll
        for (int j = 0; j < 4; j++) acc[i][j] = 0.f;

    for (int k0 = 0; k0 < CCH; k0 += 16) {
        // A tile: As[c][s] = x[b][k0+c][s0+s]   (contiguous float4, conflict-free)
        float4 av = xf4[(size_t)(k0 + ar) * (SEQ / 4) + (s0 >> 2) + ac4];
        reinterpret_cast<float4*>(As)[ar * 16 + ac4] = av;
        // B tile: Bs[c][o] = W[o0+br][k0 + bc4*4 + c]  (transpose on store)
        float4 wv = Wf4[(size_t)(o0 + br) * (CCH / 4) + (k0 >> 2) + bc4];
        Bs[(bc4 * 4 + 0) * 64 + br] = wv.x;
        Bs[(bc4 * 4 + 1) * 64 + br] = wv.y;
        Bs[(bc4 * 4 + 2) * 64 + br] = wv.z;
        Bs[(bc4 * 4 + 3) * 64 + br] = wv.w;
        __syncthreads();

#pragma unroll
        for (int k = 0; k < 16; k++) {
            float4 a4 = reinterpret_cast<const float4*>(As)[k * 16 + ty];
            float4 b4 = reinterpret_cast<const float4*>(Bs)[k * 16 + tx];
            float a[4] = {a4.x, a4.y, a4.z, a4.w};
            float bb[4] = {b4.x, b4.y, b4.z, b4.w};
#pragma unroll
            for (int i = 0; i < 4; i++)
#pragma unroll
                for (int j = 0; j < 4; j++)
                    acc[i][j] = fmaf(a[i], bb[j], acc[i][j]);
        }
        __syncthreads();
    }

    const int h  = o0 >> 6;        // one head per o-tile (o tile width == HD)
    const int bh = b * NH + h;
#pragma unroll
    for (int ii = 0; ii < 4; ii++) {
        const int s = s0 + ty * 4 + ii;
#pragma unroll
        for (int jj = 0; jj < 4; jj++) {
            const int d = tx * 4 + jj;
            const float val = acc[ii][jj] + bias[o0 + d];
            if (which == 0)
                g_q[((size_t)bh * HD + d) * SEQ + s] = val;
            else if (which == 1)
                g_k[((size_t)bh * HD + d) * SEQ + s] = val;
            else
                g_v[((size_t)bh * SEQ + s) * HD + d] = val;
        }
    }
}

// ---------------------------------------------------------------------------
// Kernel 2: flash attention.  One block = one (b,h) and one 64-query tile.
// Iterates over 64 key tiles of 64, online softmax, fp32 FFMA GEMMs.
// Dynamic smem: Qs(d-major) 16KB + Ks(d-major) 16KB + Vs(row-major) 16KB
//             + Ps (stride 65) 16.6KB = 65792 B.
// ---------------------------------------------------------------------------
extern __shared__ float fa_sm[];

__global__ __launch_bounds__(256) void flash_kernel()
{
    float* Qs = fa_sm;            // [d][i]   64*64
    float* Ks = fa_sm + 4096;     // [d][j]   64*64
    float* Vs = fa_sm + 8192;     // [j][dd]  64*64
    float* Ps = fa_sm + 12288;    // [j][i]   64 rows, stride 65

    const int t  = threadIdx.x;
    const int ty = t >> 4;        // query-row group
    const int tx = t & 15;        // key / dd-col group
    const int bh = blockIdx.y;
    const int s0 = blockIdx.x * 64;

    const float* qT = g_q + (size_t)bh * HD * SEQ;
    const float* kT = g_k + (size_t)bh * HD * SEQ;
    const float* vP = g_v + (size_t)bh * SEQ * HD;

    const int r  = t >> 2;        // staging row 0..63
    const int c4 = t & 3;         // staging float4 group

    // Stage Q (already d-major in gmem -> straight copy)
#pragma unroll
    for (int u = 0; u < 4; u++) {
        const int col4 = c4 * 4 + u;
        reinterpret_cast<float4*>(Qs)[r * 16 + col4] =
            reinterpret_cast<const float4*>(qT + (size_t)r * SEQ + s0)[col4];
    }

    float m_run[4], l_run[4], acc[4][4];
#pragma unroll
    for (int ii = 0; ii < 4; ii++) {
        m_run[ii] = -1e30f;
        l_run[ii] = 0.f;
#pragma unroll
        for (int jj = 0; jj < 4; jj++) acc[ii][jj] = 0.f;
    }

    for (int kt = 0; kt < 64; kt++) {
        __syncthreads();   // guards Q stage (iter 0) and prev-iter smem reads
        const int koff = kt * 64;
#pragma unroll
        for (int u = 0; u < 4; u++) {
            const int col4 = c4 * 4 + u;
            reinterpret_cast<float4*>(Ks)[r * 16 + col4] =
                reinterpret_cast<const float4*>(kT + (size_t)r * SEQ + koff)[col4];
            reinterpret_cast<float4*>(Vs)[r * 16 + col4] =
                reinterpret_cast<const float4*>(vP + (size_t)(koff + r) * HD)[col4];
        }
        __syncthreads();

        // S = Q K^T  (both operands d-major, float4 conflict-free)
        float sreg[4][4];
#pragma unroll
        for (int ii = 0; ii < 4; ii++)
#pragma unroll
            for (int jj = 0; jj < 4; jj++) sreg[ii][jj] = 0.f;

#pragma unroll 16
        for (int d = 0; d < 64; d++) {
            float4 a4 = reinterpret_cast<const float4*>(Qs)[d * 16 + ty];
            float4 b4 = reinterpret_cast<const float4*>(Ks)[d * 16 + tx];
            float a[4]  = {a4.x, a4.y, a4.z, a4.w};
            float bb[4] = {b4.x, b4.y, b4.z, b4.w};
#pragma unroll
            for (int ii = 0; ii < 4; ii++)
#pragma unroll
                for (int jj = 0; jj < 4; jj++)
                    sreg[ii][jj] = fmaf(a[ii], bb[jj], sreg[ii][jj]);
        }

        // online softmax per query row (16-lane row group, shfl-xor reduce)
#pragma unroll
        for (int ii = 0; ii < 4; ii++) {
#pragma unroll
            for (int jj = 0; jj < 4; jj++) sreg[ii][jj] *= 0.125f;  // 1/sqrt(64)
            float mx = fmaxf(fmaxf(sreg[ii][0], sreg[ii][1]),
                             fmaxf(sreg[ii][2], sreg[ii][3]));
            mx = fmaxf(mx, __shfl_xor_sync(0xffffffffu, mx, 1));
            mx = fmaxf(mx, __shfl_xor_sync(0xffffffffu, mx, 2));
            mx = fmaxf(mx, __shfl_xor_sync(0xffffffffu, mx, 4));
            mx = fmaxf(mx, __shfl_xor_sync(0xffffffffu, mx, 8));
            const float mnew  = fmaxf(m_run[ii], mx);
            const float alpha = __expf(m_run[ii] - mnew);
            float lsum = 0.f;
#pragma unroll
            for (int jj = 0; jj < 4; jj++) {
                const float p = __expf(sreg[ii][jj] - mnew);
                sreg[ii][jj] = p;
                lsum += p;
            }
            lsum += __shfl_xor_sync(0xffffffffu, lsum, 1);
            lsum += __shfl_xor_sync(0xffffffffu, lsum, 2);
            lsum += __shfl_xor_sync(0xffffffffu, lsum, 4);
            lsum += __shfl_xor_sync(0xffffffffu, lsum, 8);
            l_run[ii] = l_run[ii] * alpha + lsum;
            m_run[ii] = mnew;
#pragma unroll
            for (int jj = 0; jj < 4; jj++) acc[ii][jj] *= alpha;
            // stage P (j-major for PV reduction), stride 65 to dodge conflicts
#pragma unroll
            for (int jj = 0; jj < 4; jj++)
                Ps[(tx * 4 + jj) * 65 + ty * 4 + ii] = sreg[ii][jj];
        }
        __syncthreads();

        // acc += P @ V   (reduction over j; Vs naturally j-major)
#pragma unroll 8
        for (int j = 0; j < 64; j++) {
            float4 b4 = reinterpret_cast<const float4*>(Vs)[j * 16 + tx];
            float bb[4] = {b4.x, b4.y, b4.z, b4.w};
            float a[4];
#pragma unroll
            for (int ii = 0; ii < 4; ii++) a[ii] = Ps[j * 65 + ty * 4 + ii];
#pragma unroll
            for (int ii = 0; ii < 4; ii++)
#pragma unroll
                for (int jj = 0; jj < 4; jj++)
                    acc[ii][jj] = fmaf(a[ii], bb[jj], acc[ii][jj]);
        }
    }

    // epilogue: normalize, write merged-head layout [b][s][c]
    const int b = bh >> 3;
    const int h = bh & 7;
#pragma unroll
    for (int ii = 0; ii < 4; ii++) {
        const float rinv = 1.0f / l_run[ii];
        const int s = s0 + ty * 4 + ii;
        float4 o4;
        o4.x = acc[ii][0] * rinv;
        o4.y = acc[ii][1] * rinv;
        o4.z = acc[ii][2] * rinv;
        o4.w = acc[ii][3] * rinv;
        *reinterpret_cast<float4*>(
            g_o + ((size_t)b * SEQ + s) * CCH + h * HD + tx * 4) = o4;
    }
}

// ---------------------------------------------------------------------------
// Kernel 3: output projection  out = g_o @ Wp^T + bp, stored [b][c][h][w].
// ---------------------------------------------------------------------------
__global__ __launch_bounds__(256) void proj_kernel(
    const float* __restrict__ Wp, const float* __restrict__ bp,
    float* __restrict__ out)
{
    __shared__ float As[64 * 17];   // [s][c]  padded rows
    __shared__ float Bs[16 * 64];   // [c][o]  k-major

    const int t  = threadIdx.x;
    const int ty = t >> 4;
    const int tx = t & 15;
    const int s0 = blockIdx.x * 64;
    const int o0 = blockIdx.y * 64;
    const int b  = blockIdx.z;

    const float4* Af4 = reinterpret_cast<const float4*>(g_o + (size_t)b * SEQ * CCH);
    const float4* Wf4 = reinterpret_cast<const float4*>(Wp);

    const int am  = t >> 2;   // s row 0..63
    const int ak4 = t & 3;    // float4 group in k
    const int br  = t >> 2;
    const int bc4 = t & 3;

    float acc[4][4];
#pragma unroll
    for (int i = 0; i < 4; i++)
#pragma unroll
        for (int j = 0; j < 4; j++) acc[i][j] = 0.f;

    for (int k0 = 0; k0 < CCH; k0 += 16) {
        float4 av = Af4[(size_t)(s0 + am) * (CCH / 4) + (k0 >> 2) + ak4];
        As[am * 17 + ak4 * 4 + 0] = av.x;
        As[am * 17 + ak4 * 4 + 1] = av.y;
        As[am * 17 + ak4 * 4 + 2] = av.z;
        As[am * 17 + ak4 * 4 + 3] = av.w;
        float4 wv = Wf4[(size_t)(o0 + br) * (CCH / 4) + (k0 >> 2) + bc4];
        Bs[(bc4 * 4 + 0) * 64 + br] = wv.x;
        Bs[(bc4 * 4 + 1) * 64 + br] = wv.y;
        Bs[(bc4 * 4 + 2) * 64 + br] = wv.z;
        Bs[(bc4 * 4 + 3) * 64 + br] = wv.w;
        __syncthreads();

#pragma unroll
        for (int k = 0; k < 16; k++) {
            float a[4];
#pragma unroll
            for (int ii = 0; ii < 4; ii++) a[ii] = As[(ty * 4 + ii) * 17 + k];
            float4 b4 = reinterpret_cast<const float4*>(Bs)[k * 16 + tx];
            float bb[4] = {b4.x, b4.y, b4.z, b4.w};
#pragma unroll
            for (int ii = 0; ii < 4; ii++)
#pragma unroll
                for (int jj = 0; jj < 4; jj++)
                    acc[ii][jj] = fmaf(a[ii], bb[jj], acc[ii][jj]);
        }
        __syncthreads();
    }

#pragma unroll
    for (int jj = 0; jj < 4; jj++) {
        const int co = o0 + tx * 4 + jj;
        const float bias = bp[co];
#pragma unroll
        for (int ii = 0; ii < 4; ii++) {
            out[((size_t)b * CCH + co) * SEQ + s0 + ty * 4 + ii] =
                acc[ii][jj] + bias;
        }
    }
}

// ---------------------------------------------------------------------------
extern "C" void kernel_launch(void* const* d_in, const int* in_sizes, int n_in,
                              void* d_out, int out_size)
{
    const float* x  = (const float*)d_in[0];
    const float* Wq = (const float*)d_in[1];
    const float* bq = (const float*)d_in[2];
    const float* Wk = (const float*)d_in[3];
    const float* bk = (const float*)d_in[4];
    const float* Wv = (const float*)d_in[5];
    const float* bv = (const float*)d_in[6];
    const float* Wp = (const float*)d_in[7];
    const float* bp = (const float*)d_in[8];
    float* out = (float*)d_out;

    const int FA_SMEM = (4096 + 4096 + 4096 + 64 * 65) * 4;  // 65792 B
    cudaFuncSetAttribute(flash_kernel,
                         cudaFuncAttributeMaxDynamicSharedMemorySize, FA_SMEM);

    qkv_kernel<<<dim3(SEQ / 64, CCH / 64, 3 * BATCH), 256>>>(
        x, Wq, bq, Wk, bk, Wv, bv);
    flash_kernel<<<dim3(SEQ / 64, BH), 256, FA_SMEM>>>();
    proj_kernel<<<dim3(SEQ / 64, CCH / 64, BATCH), 256>>>(Wp, bp, out);
}

// round 3
// speedup vs baseline: 3.3707x; 3.3707x over previous
#include <cuda_runtime.h>
#include <math.h>

#define BATCH 2
#define CCH   512
#define SEQ   4096
#define NH    8
#define HD    64
#define BH    (BATCH*NH)

// tf32-bit scratch (allocation-free device globals)
__device__ unsigned g_q[(size_t)BH * SEQ * HD];    // [bh][s][d]
__device__ unsigned g_k[(size_t)BH * SEQ * HD];    // [bh][s][d]
__device__ unsigned g_v[(size_t)BH * HD * SEQ];    // [bh][d][s]  (transposed for PV B-operand)
__device__ unsigned g_o[(size_t)BATCH * SEQ * CCH];// [b][s][c]

__device__ __forceinline__ unsigned f2tf(float f) {
    unsigned u;
    asm("cvt.rna.tf32.f32 %0, %1;" : "=r"(u) : "f"(f));
    return u;
}

__device__ __forceinline__ void mma8(float c[4], const unsigned a[4], const unsigned b[2]) {
    asm volatile(
        "mma.sync.aligned.m16n8k8.row.col.f32.tf32.tf32.f32 "
        "{%0,%1,%2,%3}, {%4,%5,%6,%7}, {%8,%9}, {%0,%1,%2,%3};\n"
        : "+f"(c[0]), "+f"(c[1]), "+f"(c[2]), "+f"(c[3])
        : "r"(a[0]), "r"(a[1]), "r"(a[2]), "r"(a[3]), "r"(b[0]), "r"(b[1]));
}

// ---------------------------------------------------------------------------
// Kernel 1: QKV projections (tf32 mma).  A = tok (from x, [c][s] per batch),
// B = W row-major [o][c].  Block tile 128(s) x 64(o), K-chunks of 32.
// Warps 4x2 (wm: 32 rows, wn: 32 cols), each warp 2x4 m16n8 tiles.
// ---------------------------------------------------------------------------
__global__ __launch_bounds__(256) void qkv_kernel(
    const float* __restrict__ x,
    const float* __restrict__ Wq, const float* __restrict__ bq,
    const float* __restrict__ Wk, const float* __restrict__ bk,
    const float* __restrict__ Wv, const float* __restrict__ bv)
{
    __shared__ unsigned As[32 * 132];  // [c][s]  row stride 132 (128+4)
    __shared__ unsigned Bs[64 * 36];   // [o][c]  row stride 36  (32+4)

    const int t = threadIdx.x;
    const int lane = t & 31, wid = t >> 5;
    const int g = lane >> 2, t4 = lane & 3;
    const int wm = wid & 3, wn = wid >> 2;
    const int s0 = blockIdx.x * 128;
    const int o0 = blockIdx.y * 64;
    const int z  = blockIdx.z;
    const int which = z % 3, b = z / 3;

    const float *W, *bias;
    if (which == 0)      { W = Wq; bias = bq; }
    else if (which == 1) { W = Wk; bias = bk; }
    else                 { W = Wv; bias = bv; }

    const float4* xf4 = reinterpret_cast<const float4*>(x + (size_t)b * CCH * SEQ);
    const float4* Wf4 = reinterpret_cast<const float4*>(W);

    float acc[2][4][4];
#pragma unroll
    for (int i = 0; i < 2; i++)
#pragma unroll
        for (int j = 0; j < 4; j++)
#pragma unroll
            for (int q = 0; q < 4; q++) acc[i][j][q] = 0.f;

    for (int k0 = 0; k0 < CCH; k0 += 32) {
        // A tile: As[c][s] = x[b][k0+c][s0+s], tf32-converted
#pragma unroll
        for (int u = 0; u < 4; u++) {
            int idx = t + u * 256;
            int c = idx >> 5, s4 = idx & 31;
            float4 v = xf4[(size_t)(k0 + c) * (SEQ / 4) + (s0 >> 2) + s4];
            *reinterpret_cast<uint4*>(&As[c * 132 + s4 * 4]) =
                make_uint4(f2tf(v.x), f2tf(v.y), f2tf(v.z), f2tf(v.w));
        }
        // B tile: Bs[o][c] = W[o0+o][k0+c]
#pragma unroll
        for (int u = 0; u < 2; u++) {
            int idx = t + u * 256;
            int o = idx >> 3, c4 = idx & 7;
            float4 v = Wf4[(size_t)(o0 + o) * (CCH / 4) + (k0 >> 2) + c4];
            *reinterpret_cast<uint4*>(&Bs[o * 36 + c4 * 4]) =
                make_uint4(f2tf(v.x), f2tf(v.y), f2tf(v.z), f2tf(v.w));
        }
        __syncthreads();

#pragma unroll
        for (int ks = 0; ks < 4; ks++) {
            const int k = ks * 8;
            unsigned a[2][4], bf[4][2];
#pragma unroll
            for (int tm = 0; tm < 2; tm++) {
                const int s = wm * 32 + tm * 16 + g;
                a[tm][0] = As[(k + t4) * 132 + s];
                a[tm][1] = As[(k + t4) * 132 + s + 8];
                a[tm][2] = As[(k + t4 + 4) * 132 + s];
                a[tm][3] = As[(k + t4 + 4) * 132 + s + 8];
            }
#pragma unroll
            for (int tn = 0; tn < 4; tn++) {
                const int o = wn * 32 + tn * 8 + g;
                bf[tn][0] = Bs[o * 36 + k + t4];
                bf[tn][1] = Bs[o * 36 + k + t4 + 4];
            }
#pragma unroll
            for (int tm = 0; tm < 2; tm++)
#pragma unroll
                for (int tn = 0; tn < 4; tn++)
                    mma8(acc[tm][tn], a[tm], bf[tn]);
        }
        __syncthreads();
    }

    // Epilogue: bias, convert to tf32, store to the flash-friendly layouts.
    const int h  = o0 >> 6;   // N-tile width == HD
    const int bh = b * NH + h;
#pragma unroll
    for (int tm = 0; tm < 2; tm++) {
#pragma unroll
        for (int tn = 0; tn < 4; tn++) {
            const int col0 = wn * 32 + tn * 8 + 2 * t4;
            const float b0 = bias[o0 + col0];
            const float b1 = bias[o0 + col0 + 1];
#pragma unroll
            for (int half = 0; half < 2; half++) {
                const int s = s0 + wm * 32 + tm * 16 + g + half * 8;
                const float v0 = acc[tm][tn][half * 2 + 0] + b0;
                const float v1 = acc[tm][tn][half * 2 + 1] + b1;
                if (which == 0) {
                    *reinterpret_cast<uint2*>(&g_q[((size_t)bh * SEQ + s) * HD + col0]) =
                        make_uint2(f2tf(v0), f2tf(v1));
                } else if (which == 1) {
                    *reinterpret_cast<uint2*>(&g_k[((size_t)bh * SEQ + s) * HD + col0]) =
                        make_uint2(f2tf(v0), f2tf(v1));
                } else {
                    g_v[((size_t)bh * HD + col0) * SEQ + s]     = f2tf(v0);
                    g_v[((size_t)bh * HD + col0 + 1) * SEQ + s] = f2tf(v1);
                }
            }
        }
    }
}

// ---------------------------------------------------------------------------
// Kernel 2: flash attention (tf32 mma).  Block = 128 queries x one (b,h).
// 8 warps, each owns 16 query rows x all 64 keys (row reductions stay in-quad).
// smem rows stride 68 -> conflict-free fragment LDS.
// ---------------------------------------------------------------------------
extern __shared__ unsigned fa_sh[];

__global__ __launch_bounds__(256) void flash_kernel()
{
    unsigned* Qs = fa_sh;                 // [128][68]
    unsigned* Ks = fa_sh + 128 * 68;      // [64][68]
    unsigned* Vs = Ks + 64 * 68;          // [64][68]   Vs[dd][j]
    unsigned* Ps = Vs + 64 * 68;          // [128][68]

    const int t = threadIdx.x, lane = t & 31, wid = t >> 5;
    const int g = lane >> 2, t4 = lane & 3;
    const int bh = blockIdx.y, s0 = blockIdx.x * 128;
    const int b = bh >> 3, h = bh & 7;

    const unsigned* qP = g_q + (size_t)bh * SEQ * HD;
    const unsigned* kP = g_k + (size_t)bh * SEQ * HD;
    const unsigned* vP = g_v + (size_t)bh * HD * SEQ;

    // Stage Q (already tf32, row-major [s][d])
#pragma unroll
    for (int u = 0; u < 8; u++) {
        int idx = t + u * 256;
        int r = idx >> 4, c4 = idx & 15;
        *reinterpret_cast<uint4*>(&Qs[r * 68 + c4 * 4]) =
            reinterpret_cast<const uint4*>(qP + (size_t)(s0 + r) * HD)[c4];
    }

    float m0 = -1e30f, m1 = -1e30f, l0 = 0.f, l1 = 0.f;
    float oacc[8][4];
#pragma unroll
    for (int i = 0; i < 8; i++)
#pragma unroll
        for (int j = 0; j < 4; j++) oacc[i][j] = 0.f;

    const int row = wid * 16 + g;

    for (int kt = 0; kt < 64; kt++) {
        __syncthreads();
        const int koff = kt * 64;
#pragma unroll
        for (int u = 0; u < 4; u++) {
            int idx = t + u * 256;
            int r = idx >> 4, c4 = idx & 15;
            *reinterpret_cast<uint4*>(&Ks[r * 68 + c4 * 4]) =
                reinterpret_cast<const uint4*>(kP + (size_t)(koff + r) * HD)[c4];
            *reinterpret_cast<uint4*>(&Vs[r * 68 + c4 * 4]) =
                reinterpret_cast<const uint4*>(vP + (size_t)r * SEQ + koff)[c4];
        }
        __syncthreads();

        // S = Q K^T   (16 x 64 per warp)
        float s_f[8][4];
#pragma unroll
        for (int i = 0; i < 8; i++)
#pragma unroll
            for (int j = 0; j < 4; j++) s_f[i][j] = 0.f;

#pragma unroll
        for (int ks = 0; ks < 8; ks++) {
            unsigned a[4];
            a[0] = Qs[row * 68 + ks * 8 + t4];
            a[1] = Qs[(row + 8) * 68 + ks * 8 + t4];
            a[2] = Qs[row * 68 + ks * 8 + t4 + 4];
            a[3] = Qs[(row + 8) * 68 + ks * 8 + t4 + 4];
#pragma unroll
            for (int tn = 0; tn < 8; tn++) {
                unsigned bb[2];
                const int n = tn * 8 + g;
                bb[0] = Ks[n * 68 + ks * 8 + t4];
                bb[1] = Ks[n * 68 + ks * 8 + t4 + 4];
                mma8(s_f[tn], a, bb);
            }
        }

        // online softmax (rows g and g+8; full row lives in this quad)
        float mx0 = -1e30f, mx1 = -1e30f;
#pragma unroll
        for (int tn = 0; tn < 8; tn++) {
#pragma unroll
            for (int j = 0; j < 4; j++) s_f[tn][j] *= 0.125f;  // 1/sqrt(64)
            mx0 = fmaxf(mx0, fmaxf(s_f[tn][0], s_f[tn][1]));
            mx1 = fmaxf(mx1, fmaxf(s_f[tn][2], s_f[tn][3]));
        }
        mx0 = fmaxf(mx0, __shfl_xor_sync(0xffffffffu, mx0, 1));
        mx0 = fmaxf(mx0, __shfl_xor_sync(0xffffffffu, mx0, 2));
        mx1 = fmaxf(mx1, __shfl_xor_sync(0xffffffffu, mx1, 1));
        mx1 = fmaxf(mx1, __shfl_xor_sync(0xffffffffu, mx1, 2));

        const float nm0 = fmaxf(m0, mx0), nm1 = fmaxf(m1, mx1);
        const float al0 = __expf(m0 - nm0), al1 = __expf(m1 - nm1);
        float ls0 = 0.f, ls1 = 0.f;
#pragma unroll
        for (int tn = 0; tn < 8; tn++) {
            s_f[tn][0] = __expf(s_f[tn][0] - nm0);
            s_f[tn][1] = __expf(s_f[tn][1] - nm0);
            s_f[tn][2] = __expf(s_f[tn][2] - nm1);
            s_f[tn][3] = __expf(s_f[tn][3] - nm1);
            ls0 += s_f[tn][0] + s_f[tn][1];
            ls1 += s_f[tn][2] + s_f[tn][3];
        }
        ls0 += __shfl_xor_sync(0xffffffffu, ls0, 1);
        ls0 += __shfl_xor_sync(0xffffffffu, ls0, 2);
        ls1 += __shfl_xor_sync(0xffffffffu, ls1, 1);
        ls1 += __shfl_xor_sync(0xffffffffu, ls1, 2);
        l0 = l0 * al0 + ls0;  m0 = nm0;
        l1 = l1 * al1 + ls1;  m1 = nm1;

#pragma unroll
        for (int tn = 0; tn < 8; tn++) {
            oacc[tn][0] *= al0; oacc[tn][1] *= al0;
            oacc[tn][2] *= al1; oacc[tn][3] *= al1;
            // stage P (tf32) into this warp's private rows
            *reinterpret_cast<uint2*>(&Ps[row * 68 + tn * 8 + 2 * t4]) =
                make_uint2(f2tf(s_f[tn][0]), f2tf(s_f[tn][1]));
            *reinterpret_cast<uint2*>(&Ps[(row + 8) * 68 + tn * 8 + 2 * t4]) =
                make_uint2(f2tf(s_f[tn][2]), f2tf(s_f[tn][3]));
        }
        __syncwarp();

        // O += P V   (reduction over j; Vs[dd][j] is the col-major B)
#pragma unroll
        for (int ks = 0; ks < 8; ks++) {
            unsigned a[4];
            a[0] = Ps[row * 68 + ks * 8 + t4];
            a[1] = Ps[(row + 8) * 68 + ks * 8 + t4];
            a[2] = Ps[row * 68 + ks * 8 + t4 + 4];
            a[3] = Ps[(row + 8) * 68 + ks * 8 + t4 + 4];
#pragma unroll
            for (int tn = 0; tn < 8; tn++) {
                unsigned bb[2];
                const int n = tn * 8 + g;
                bb[0] = Vs[n * 68 + ks * 8 + t4];
                bb[1] = Vs[n * 68 + ks * 8 + t4 + 4];
                mma8(oacc[tn], a, bb);
            }
        }
    }

    // epilogue: normalize + store tf32 to merged-head [b][s][c]
    const float r0 = 1.f / l0, r1 = 1.f / l1;
    const int srow = s0 + row;
#pragma unroll
    for (int tn = 0; tn < 8; tn++) {
        const int c = h * 64 + tn * 8 + 2 * t4;
        *reinterpret_cast<uint2*>(&g_o[((size_t)b * SEQ + srow) * CCH + c]) =
            make_uint2(f2tf(oacc[tn][0] * r0), f2tf(oacc[tn][1] * r0));
        *reinterpret_cast<uint2*>(&g_o[((size_t)b * SEQ + srow + 8) * CCH + c]) =
            make_uint2(f2tf(oacc[tn][2] * r1), f2tf(oacc[tn][3] * r1));
    }
}

// ---------------------------------------------------------------------------
// Kernel 3: out-projection (tf32 mma) + transposed fp32 store to [b][c][h][w].
// ---------------------------------------------------------------------------
__global__ __launch_bounds__(256) void proj_kernel(
    const float* __restrict__ Wp, const float* __restrict__ bp,
    float* __restrict__ out)
{
    __shared__ unsigned As[128 * 36];  // [s][c] stride 36
    __shared__ unsigned Bs[64 * 36];   // [o][c] stride 36

    const int t = threadIdx.x;
    const int lane = t & 31, wid = t >> 5;
    const int g = lane >> 2, t4 = lane & 3;
    const int wm = wid & 3, wn = wid >> 2;
    const int s0 = blockIdx.x * 128;
    const int o0 = blockIdx.y * 64;
    const int b  = blockIdx.z;

    const float4* Wf4 = reinterpret_cast<const float4*>(Wp);

    float acc[2][4][4];
#pragma unroll
    for (int i = 0; i < 2; i++)
#pragma unroll
        for (int j = 0; j < 4; j++)
#pragma unroll
            for (int q = 0; q < 4; q++) acc[i][j][q] = 0.f;

    for (int k0 = 0; k0 < CCH; k0 += 32) {
        // A tile: g_o already tf32, row-major [s][c]
#pragma unroll
        for (int u = 0; u < 4; u++) {
            int idx = t + u * 256;
            int r = idx >> 3, c4 = idx & 7;
            *reinterpret_cast<uint4*>(&As[r * 36 + c4 * 4]) =
                reinterpret_cast<const uint4*>(
                    g_o + ((size_t)b * SEQ + s0 + r) * CCH + k0)[c4];
        }
#pragma unroll
        for (int u = 0; u < 2; u++) {
            int idx = t + u * 256;
            int o = idx >> 3, c4 = idx & 7;
            float4 v = Wf4[(size_t)(o0 + o) * (CCH / 4) + (k0 >> 2) + c4];
            *reinterpret_cast<uint4*>(&Bs[o * 36 + c4 * 4]) =
                make_uint4(f2tf(v.x), f2tf(v.y), f2tf(v.z), f2tf(v.w));
        }
        __syncthreads();

#pragma unroll
        for (int ks = 0; ks < 4; ks++) {
            const int k = ks * 8;
            unsigned a[2][4], bf[4][2];
#pragma unroll
            for (int tm = 0; tm < 2; tm++) {
                const int s = wm * 32 + tm * 16 + g;
                a[tm][0] = As[s * 36 + k + t4];
                a[tm][1] = As[(s + 8) * 36 + k + t4];
                a[tm][2] = As[s * 36 + k + t4 + 4];
                a[tm][3] = As[(s + 8) * 36 + k + t4 + 4];
            }
#pragma unroll
            for (int tn = 0; tn < 4; tn++) {
                const int o = wn * 32 + tn * 8 + g;
                bf[tn][0] = Bs[o * 36 + k + t4];
                bf[tn][1] = Bs[o * 36 + k + t4 + 4];
            }
#pragma unroll
            for (int tm = 0; tm < 2; tm++)
#pragma unroll
                for (int tn = 0; tn < 4; tn++)
                    mma8(acc[tm][tn], a[tm], bf[tn]);
        }
        __syncthreads();
    }

#pragma unroll
    for (int tm = 0; tm < 2; tm++) {
#pragma unroll
        for (int tn = 0; tn < 4; tn++) {
            const int col0 = o0 + wn * 32 + tn * 8 + 2 * t4;
            const float b0 = bp[col0], b1 = bp[col0 + 1];
#pragma unroll
            for (int half = 0; half < 2; half++) {
                const int s = s0 + wm * 32 + tm * 16 + g + half * 8;
                out[((size_t)b * CCH + col0) * SEQ + s]     = acc[tm][tn][half * 2 + 0] + b0;
                out[((size_t)b * CCH + col0 + 1) * SEQ + s] = acc[tm][tn][half * 2 + 1] + b1;
            }
        }
    }
}

// ---------------------------------------------------------------------------
extern "C" void kernel_launch(void* const* d_in, const int* in_sizes, int n_in,
                              void* d_out, int out_size)
{
    const float* x  = (const float*)d_in[0];
    const float* Wq = (const float*)d_in[1];
    const float* bq = (const float*)d_in[2];
    const float* Wk = (const float*)d_in[3];
    const float* bk = (const float*)d_in[4];
    const float* Wv = (const float*)d_in[5];
    const float* bv = (const float*)d_in[6];
    const float* Wp = (const float*)d_in[7];
    const float* bp = (const float*)d_in[8];
    float* out = (float*)d_out;

    const int FA_SMEM = (128 * 68 + 64 * 68 + 64 * 68 + 128 * 68) * 4;  // 104448 B
    cudaFuncSetAttribute(flash_kernel,
                         cudaFuncAttributeMaxDynamicSharedMemorySize, FA_SMEM);

    qkv_kernel<<<dim3(SEQ / 128, CCH / 64, 3 * BATCH), 256>>>(
        x, Wq, bq, Wk, bk, Wv, bv);
    flash_kernel<<<dim3(SEQ / 128, BH), 256, FA_SMEM>>>();
    proj_kernel<<<dim3(SEQ / 128, CCH / 64, BATCH), 256>>>(Wp, bp, out);
}

// round 4
// speedup vs baseline: 3.6993x; 1.0975x over previous
#include <cuda_runtime.h>
#include <math.h>

#define BATCH 2
#define CCH   512
#define SEQ   4096
#define NH    8
#define HD    64
#define BH    (BATCH*NH)

// tf32-bit scratch (allocation-free device globals)
__device__ unsigned g_q[(size_t)BH * SEQ * HD];    // [bh][s][d]
__device__ unsigned g_k[(size_t)BH * SEQ * HD];    // [bh][s][d]
__device__ unsigned g_v[(size_t)BH * HD * SEQ];    // [bh][d][s]
__device__ unsigned g_o[(size_t)BATCH * SEQ * CCH];// [b][s][c]

__device__ __forceinline__ unsigned f2tf(float f) {
    unsigned u;
    asm("cvt.rna.tf32.f32 %0, %1;" : "=r"(u) : "f"(f));
    return u;
}

__device__ __forceinline__ void mma8(float c[4], const unsigned a[4], const unsigned b[2]) {
    asm volatile(
        "mma.sync.aligned.m16n8k8.row.col.f32.tf32.tf32.f32 "
        "{%0,%1,%2,%3}, {%4,%5,%6,%7}, {%8,%9}, {%0,%1,%2,%3};\n"
        : "+f"(c[0]), "+f"(c[1]), "+f"(c[2]), "+f"(c[3])
        : "r"(a[0]), "r"(a[1]), "r"(a[2]), "r"(a[3]), "r"(b[0]), "r"(b[1]));
}

__device__ __forceinline__ void cp16(unsigned* smem_dst, const unsigned* gmem_src) {
    unsigned sa = (unsigned)__cvta_generic_to_shared(smem_dst);
    asm volatile("cp.async.cg.shared.global [%0], [%1], 16;" :: "r"(sa), "l"(gmem_src));
}
#define CP_COMMIT() asm volatile("cp.async.commit_group;")
#define CP_WAIT0()  asm volatile("cp.async.wait_group 0;")

// ---------------------------------------------------------------------------
// Kernel 1: QKV projections (tf32 mma).  Block tile 128(s) x 64(o), K=32 chunks.
// ---------------------------------------------------------------------------
__global__ __launch_bounds__(256) void qkv_kernel(
    const float* __restrict__ x,
    const float* __restrict__ Wq, const float* __restrict__ bq,
    const float* __restrict__ Wk, const float* __restrict__ bk,
    const float* __restrict__ Wv, const float* __restrict__ bv)
{
    __shared__ unsigned As[32 * 132];  // [c][s]  stride 132
    __shared__ unsigned Bs[64 * 36];   // [o][c]  stride 36

    const int t = threadIdx.x;
    const int lane = t & 31, wid = t >> 5;
    const int g = lane >> 2, t4 = lane & 3;
    const int wm = wid & 3, wn = wid >> 2;
    const int s0 = blockIdx.x * 128;
    const int o0 = blockIdx.y * 64;
    const int z  = blockIdx.z;
    const int which = z % 3, b = z / 3;

    const float *W, *bias;
    if (which == 0)      { W = Wq; bias = bq; }
    else if (which == 1) { W = Wk; bias = bk; }
    else                 { W = Wv; bias = bv; }

    const float4* xf4 = reinterpret_cast<const float4*>(x + (size_t)b * CCH * SEQ);
    const float4* Wf4 = reinterpret_cast<const float4*>(W);

    float acc[2][4][4];
#pragma unroll
    for (int i = 0; i < 2; i++)
#pragma unroll
        for (int j = 0; j < 4; j++)
#pragma unroll
            for (int q = 0; q < 4; q++) acc[i][j][q] = 0.f;

    for (int k0 = 0; k0 < CCH; k0 += 32) {
#pragma unroll
        for (int u = 0; u < 4; u++) {
            int idx = t + u * 256;
            int c = idx >> 5, s4 = idx & 31;
            float4 v = xf4[(size_t)(k0 + c) * (SEQ / 4) + (s0 >> 2) + s4];
            *reinterpret_cast<uint4*>(&As[c * 132 + s4 * 4]) =
                make_uint4(f2tf(v.x), f2tf(v.y), f2tf(v.z), f2tf(v.w));
        }
#pragma unroll
        for (int u = 0; u < 2; u++) {
            int idx = t + u * 256;
            int o = idx >> 3, c4 = idx & 7;
            float4 v = Wf4[(size_t)(o0 + o) * (CCH / 4) + (k0 >> 2) + c4];
            *reinterpret_cast<uint4*>(&Bs[o * 36 + c4 * 4]) =
                make_uint4(f2tf(v.x), f2tf(v.y), f2tf(v.z), f2tf(v.w));
        }
        __syncthreads();

#pragma unroll
        for (int ks = 0; ks < 4; ks++) {
            const int k = ks * 8;
            unsigned a[2][4], bf[4][2];
#pragma unroll
            for (int tm = 0; tm < 2; tm++) {
                const int s = wm * 32 + tm * 16 + g;
                a[tm][0] = As[(k + t4) * 132 + s];
                a[tm][1] = As[(k + t4) * 132 + s + 8];
                a[tm][2] = As[(k + t4 + 4) * 132 + s];
                a[tm][3] = As[(k + t4 + 4) * 132 + s + 8];
            }
#pragma unroll
            for (int tn = 0; tn < 4; tn++) {
                const int o = wn * 32 + tn * 8 + g;
                bf[tn][0] = Bs[o * 36 + k + t4];
                bf[tn][1] = Bs[o * 36 + k + t4 + 4];
            }
#pragma unroll
            for (int tm = 0; tm < 2; tm++)
#pragma unroll
                for (int tn = 0; tn < 4; tn++)
                    mma8(acc[tm][tn], a[tm], bf[tn]);
        }
        __syncthreads();
    }

    const int h  = o0 >> 6;
    const int bh = b * NH + h;
#pragma unroll
    for (int tm = 0; tm < 2; tm++) {
#pragma unroll
        for (int tn = 0; tn < 4; tn++) {
            const int col0 = wn * 32 + tn * 8 + 2 * t4;
            const float b0 = bias[o0 + col0];
            const float b1 = bias[o0 + col0 + 1];
#pragma unroll
            for (int half = 0; half < 2; half++) {
                const int s = s0 + wm * 32 + tm * 16 + g + half * 8;
                const float v0 = acc[tm][tn][half * 2 + 0] + b0;
                const float v1 = acc[tm][tn][half * 2 + 1] + b1;
                if (which == 0) {
                    *reinterpret_cast<uint2*>(&g_q[((size_t)bh * SEQ + s) * HD + col0]) =
                        make_uint2(f2tf(v0), f2tf(v1));
                } else if (which == 1) {
                    *reinterpret_cast<uint2*>(&g_k[((size_t)bh * SEQ + s) * HD + col0]) =
                        make_uint2(f2tf(v0), f2tf(v1));
                } else {
                    g_v[((size_t)bh * HD + col0) * SEQ + s]     = f2tf(v0);
                    g_v[((size_t)bh * HD + col0 + 1) * SEQ + s] = f2tf(v1);
                }
            }
        }
    }
}

// ---------------------------------------------------------------------------
// Kernel 2: flash attention.  128-query tile, 8 warps x 16 rows.
// cp.async double-buffered K/V; Q fragments register-cached; Q smem aliased
// as P staging buffer (warp-private rows); exp2-domain softmax.
// smem: QP 128x68 + K 2x64x68 + V 2x64x68 = 104448 B  -> 2 blocks/SM.
// ---------------------------------------------------------------------------
extern __shared__ unsigned fa_sh[];

__global__ void __launch_bounds__(256, 2) flash_kernel()
{
    unsigned* QP  = fa_sh;                 // [128][68]  Q, later P
    unsigned* Kb0 = fa_sh + 8704;          // [64][68]
    unsigned* Kb1 = Kb0 + 4352;
    unsigned* Vb0 = Kb1 + 4352;            // Vs[dd][j]
    unsigned* Vb1 = Vb0 + 4352;

    const int t = threadIdx.x, lane = t & 31, wid = t >> 5;
    const int g = lane >> 2, t4 = lane & 3;
    const int bh = blockIdx.y, s0 = blockIdx.x * 128;
    const int b = bh >> 3, h = bh & 7;

    const unsigned* qPtr = g_q + (size_t)bh * SEQ * HD;
    const unsigned* kPtr = g_k + (size_t)bh * SEQ * HD;
    const unsigned* vPtr = g_v + (size_t)bh * HD * SEQ;

    // ---- prologue: stage Q (uint4) + K0/V0 (cp.async) ----
#pragma unroll
    for (int u = 0; u < 8; u++) {
        int idx = t + u * 256;
        int r = idx >> 4, c4 = idx & 15;
        *reinterpret_cast<uint4*>(&QP[r * 68 + c4 * 4]) =
            reinterpret_cast<const uint4*>(qPtr + (size_t)(s0 + r) * HD)[c4];
    }
#pragma unroll
    for (int u = 0; u < 4; u++) {
        int idx = t + u * 256;
        int r = idx >> 4, c4 = idx & 15;
        cp16(&Kb0[r * 68 + c4 * 4], kPtr + (size_t)r * HD + c4 * 4);
        cp16(&Vb0[r * 68 + c4 * 4], vPtr + (size_t)r * SEQ + c4 * 4);
    }
    CP_COMMIT();
    CP_WAIT0();
    __syncthreads();

    // ---- cache Q fragments (warp-private rows), then QP becomes P buffer ----
    const int row = wid * 16 + g;
    unsigned qf[8][4];
#pragma unroll
    for (int ks = 0; ks < 8; ks++) {
        qf[ks][0] = QP[row * 68 + ks * 8 + t4];
        qf[ks][1] = QP[(row + 8) * 68 + ks * 8 + t4];
        qf[ks][2] = QP[row * 68 + ks * 8 + t4 + 4];
        qf[ks][3] = QP[(row + 8) * 68 + ks * 8 + t4 + 4];
    }
    __syncwarp();

    const float SC = 0.125f * 1.44269504088896f;   // 1/sqrt(64) * log2(e)
    float m0 = -1e30f, m1 = -1e30f, l0 = 0.f, l1 = 0.f;
    float oacc[8][4];
#pragma unroll
    for (int i = 0; i < 8; i++)
#pragma unroll
        for (int j = 0; j < 4; j++) oacc[i][j] = 0.f;

    for (int kt = 0; kt < 64; kt++) {
        unsigned* Kc = (kt & 1) ? Kb1 : Kb0;
        unsigned* Vc = (kt & 1) ? Vb1 : Vb0;

        // prefetch next tile into the other buffer (background)
        if (kt < 63) {
            unsigned* Kn = (kt & 1) ? Kb0 : Kb1;
            unsigned* Vn = (kt & 1) ? Vb0 : Vb1;
            const int koff = (kt + 1) * 64;
#pragma unroll
            for (int u = 0; u < 4; u++) {
                int idx = t + u * 256;
                int r = idx >> 4, c4 = idx & 15;
                cp16(&Kn[r * 68 + c4 * 4], kPtr + (size_t)(koff + r) * HD + c4 * 4);
                cp16(&Vn[r * 68 + c4 * 4], vPtr + (size_t)r * SEQ + koff + c4 * 4);
            }
            CP_COMMIT();
        }

        // ---- S = Q K^T (16x64 per warp) ----
        float s_f[8][4];
#pragma unroll
        for (int i = 0; i < 8; i++)
#pragma unroll
            for (int j = 0; j < 4; j++) s_f[i][j] = 0.f;

#pragma unroll
        for (int ks = 0; ks < 8; ks++) {
#pragma unroll
            for (int tn = 0; tn < 8; tn++) {
                unsigned bb[2];
                const int n = tn * 8 + g;
                bb[0] = Kc[n * 68 + ks * 8 + t4];
                bb[1] = Kc[n * 68 + ks * 8 + t4 + 4];
                mma8(s_f[tn], qf[ks], bb);
            }
        }

        // ---- online softmax, exp2 domain ----
        float mx0 = -1e30f, mx1 = -1e30f;
#pragma unroll
        for (int tn = 0; tn < 8; tn++) {
#pragma unroll
            for (int j = 0; j < 4; j++) s_f[tn][j] *= SC;
            mx0 = fmaxf(mx0, fmaxf(s_f[tn][0], s_f[tn][1]));
            mx1 = fmaxf(mx1, fmaxf(s_f[tn][2], s_f[tn][3]));
        }
        mx0 = fmaxf(mx0, __shfl_xor_sync(0xffffffffu, mx0, 1));
        mx0 = fmaxf(mx0, __shfl_xor_sync(0xffffffffu, mx0, 2));
        mx1 = fmaxf(mx1, __shfl_xor_sync(0xffffffffu, mx1, 1));
        mx1 = fmaxf(mx1, __shfl_xor_sync(0xffffffffu, mx1, 2));

        const float nm0 = fmaxf(m0, mx0), nm1 = fmaxf(m1, mx1);
        const float al0 = exp2f(m0 - nm0), al1 = exp2f(m1 - nm1);
        float ls0 = 0.f, ls1 = 0.f;
#pragma unroll
        for (int tn = 0; tn < 8; tn++) {
            s_f[tn][0] = exp2f(s_f[tn][0] - nm0);
            s_f[tn][1] = exp2f(s_f[tn][1] - nm0);
            s_f[tn][2] = exp2f(s_f[tn][2] - nm1);
            s_f[tn][3] = exp2f(s_f[tn][3] - nm1);
            ls0 += s_f[tn][0] + s_f[tn][1];
            ls1 += s_f[tn][2] + s_f[tn][3];
        }
        ls0 += __shfl_xor_sync(0xffffffffu, ls0, 1);
        ls0 += __shfl_xor_sync(0xffffffffu, ls0, 2);
        ls1 += __shfl_xor_sync(0xffffffffu, ls1, 1);
        ls1 += __shfl_xor_sync(0xffffffffu, ls1, 2);
        l0 = l0 * al0 + ls0;  m0 = nm0;
        l1 = l1 * al1 + ls1;  m1 = nm1;

        // ---- stage P into warp-private rows of QP ----
#pragma unroll
        for (int tn = 0; tn < 8; tn++) {
            oacc[tn][0] *= al0; oacc[tn][1] *= al0;
            oacc[tn][2] *= al1; oacc[tn][3] *= al1;
            *reinterpret_cast<uint2*>(&QP[row * 68 + tn * 8 + 2 * t4]) =
                make_uint2(f2tf(s_f[tn][0]), f2tf(s_f[tn][1]));
            *reinterpret_cast<uint2*>(&QP[(row + 8) * 68 + tn * 8 + 2 * t4]) =
                make_uint2(f2tf(s_f[tn][2]), f2tf(s_f[tn][3]));
        }
        __syncwarp();

        // ---- O += P V ----
#pragma unroll
        for (int ks = 0; ks < 8; ks++) {
            unsigned a[4];
            a[0] = QP[row * 68 + ks * 8 + t4];
            a[1] = QP[(row + 8) * 68 + ks * 8 + t4];
            a[2] = QP[row * 68 + ks * 8 + t4 + 4];
            a[3] = QP[(row + 8) * 68 + ks * 8 + t4 + 4];
#pragma unroll
            for (int tn = 0; tn < 8; tn++) {
                unsigned bb[2];
                const int n = tn * 8 + g;
                bb[0] = Vc[n * 68 + ks * 8 + t4];
                bb[1] = Vc[n * 68 + ks * 8 + t4 + 4];
                mma8(oacc[tn], a, bb);
            }
        }

        if (kt < 63) {
            CP_WAIT0();
            __syncthreads();
        }
    }

    // ---- epilogue: normalize + store tf32 to [b][s][c] ----
    const float r0 = 1.f / l0, r1 = 1.f / l1;
    const int srow = s0 + row;
#pragma unroll
    for (int tn = 0; tn < 8; tn++) {
        const int c = h * 64 + tn * 8 + 2 * t4;
        *reinterpret_cast<uint2*>(&g_o[((size_t)b * SEQ + srow) * CCH + c]) =
            make_uint2(f2tf(oacc[tn][0] * r0), f2tf(oacc[tn][1] * r0));
        *reinterpret_cast<uint2*>(&g_o[((size_t)b * SEQ + srow + 8) * CCH + c]) =
            make_uint2(f2tf(oacc[tn][2] * r1), f2tf(oacc[tn][3] * r1));
    }
}

// ---------------------------------------------------------------------------
// Kernel 3: out-projection (tf32 mma) + transposed fp32 store to [b][c][h][w].
// ---------------------------------------------------------------------------
__global__ __launch_bounds__(256) void proj_kernel(
    const float* __restrict__ Wp, const float* __restrict__ bp,
    float* __restrict__ out)
{
    __shared__ unsigned As[128 * 36];  // [s][c] stride 36
    __shared__ unsigned Bs[64 * 36];   // [o][c] stride 36

    const int t = threadIdx.x;
    const int lane = t & 31, wid = t >> 5;
    const int g = lane >> 2, t4 = lane & 3;
    const int wm = wid & 3, wn = wid >> 2;
    const int s0 = blockIdx.x * 128;
    const int o0 = blockIdx.y * 64;
    const int b  = blockIdx.z;

    const float4* Wf4 = reinterpret_cast<const float4*>(Wp);

    float acc[2][4][4];
#pragma unroll
    for (int i = 0; i < 2; i++)
#pragma unroll
        for (int j = 0; j < 4; j++)
#pragma unroll
            for (int q = 0; q < 4; q++) acc[i][j][q] = 0.f;

    for (int k0 = 0; k0 < CCH; k0 += 32) {
#pragma unroll
        for (int u = 0; u < 4; u++) {
            int idx = t + u * 256;
            int r = idx >> 3, c4 = idx & 7;
            *reinterpret_cast<uint4*>(&As[r * 36 + c4 * 4]) =
                reinterpret_cast<const uint4*>(
                    g_o + ((size_t)b * SEQ + s0 + r) * CCH + k0)[c4];
        }
#pragma unroll
        for (int u = 0; u < 2; u++) {
            int idx = t + u * 256;
            int o = idx >> 3, c4 = idx & 7;
            float4 v = Wf4[(size_t)(o0 + o) * (CCH / 4) + (k0 >> 2) + c4];
            *reinterpret_cast<uint4*>(&Bs[o * 36 + c4 * 4]) =
                make_uint4(f2tf(v.x), f2tf(v.y), f2tf(v.z), f2tf(v.w));
        }
        __syncthreads();

#pragma unroll
        for (int ks = 0; ks < 4; ks++) {
            const int k = ks * 8;
            unsigned a[2][4], bf[4][2];
#pragma unroll
            for (int tm = 0; tm < 2; tm++) {
                const int s = wm * 32 + tm * 16 + g;
                a[tm][0] = As[s * 36 + k + t4];
                a[tm][1] = As[(s + 8) * 36 + k + t4];
                a[tm][2] = As[s * 36 + k + t4 + 4];
                a[tm][3] = As[(s + 8) * 36 + k + t4 + 4];
            }
#pragma unroll
            for (int tn = 0; tn < 4; tn++) {
                const int o = wn * 32 + tn * 8 + g;
                bf[tn][0] = Bs[o * 36 + k + t4];
                bf[tn][1] = Bs[o * 36 + k + t4 + 4];
            }
#pragma unroll
            for (int tm = 0; tm < 2; tm++)
#pragma unroll
                for (int tn = 0; tn < 4; tn++)
                    mma8(acc[tm][tn], a[tm], bf[tn]);
        }
        __syncthreads();
    }

#pragma unroll
    for (int tm = 0; tm < 2; tm++) {
#pragma unroll
        for (int tn = 0; tn < 4; tn++) {
            const int col0 = o0 + wn * 32 + tn * 8 + 2 * t4;
            const float b0 = bp[col0], b1 = bp[col0 + 1];
#pragma unroll
            for (int half = 0; half < 2; half++) {
                const int s = s0 + wm * 32 + tm * 16 + g + half * 8;
                out[((size_t)b * CCH + col0) * SEQ + s]     = acc[tm][tn][half * 2 + 0] + b0;
                out[((size_t)b * CCH + col0 + 1) * SEQ + s] = acc[tm][tn][half * 2 + 1] + b1;
            }
        }
    }
}

// ---------------------------------------------------------------------------
extern "C" void kernel_launch(void* const* d_in, const int* in_sizes, int n_in,
                              void* d_out, int out_size)
{
    const float* x  = (const float*)d_in[0];
    const float* Wq = (const float*)d_in[1];
    const float* bq = (const float*)d_in[2];
    const float* Wk = (const float*)d_in[3];
    const float* bk = (const float*)d_in[4];
    const float* Wv = (const float*)d_in[5];
    const float* bv = (const float*)d_in[6];
    const float* Wp = (const float*)d_in[7];
    const float* bp = (const float*)d_in[8];
    float* out = (float*)d_out;

    const int FA_SMEM = (128 * 68 + 4 * 64 * 68) * 4;  // 104448 B
    cudaFuncSetAttribute(flash_kernel,
                         cudaFuncAttributeMaxDynamicSharedMemorySize, FA_SMEM);

    qkv_kernel<<<dim3(SEQ / 128, CCH / 64, 3 * BATCH), 256>>>(
        x, Wq, bq, Wk, bk, Wv, bv);
    flash_kernel<<<dim3(SEQ / 128, BH), 256, FA_SMEM>>>();
    proj_kernel<<<dim3(SEQ / 128, CCH / 64, BATCH), 256>>>(Wp, bp, out);
}

// round 5
// speedup vs baseline: 6.9519x; 1.8793x over previous
#include <cuda_runtime.h>
#include <cuda_fp16.h>
#include <math.h>

#define BATCH 2
#define CCH   512
#define SEQ   4096
#define NH    8
#define HD    64
#define BH    (BATCH*NH)

// fp16 scratch (allocation-free device globals)
__device__ __half g_tok[(size_t)BATCH * SEQ * CCH]; // [b][s][c]
__device__ __half g_q16[(size_t)BH * SEQ * HD];     // [bh][s][d]
__device__ __half g_k16[(size_t)BH * SEQ * HD];     // [bh][s][d]
__device__ __half g_v16[(size_t)BH * HD * SEQ];     // [bh][d][s]
__device__ __half g_o16[(size_t)BATCH * SEQ * CCH]; // [b][s][c]

__device__ __forceinline__ unsigned pack2(float lo, float hi) {
    __half2 h = __floats2half2_rn(lo, hi);
    return *reinterpret_cast<unsigned*>(&h);
}

__device__ __forceinline__ void mma16(float c[4], const unsigned a[4], const unsigned b[2]) {
    asm volatile(
        "mma.sync.aligned.m16n8k16.row.col.f32.f16.f16.f32 "
        "{%0,%1,%2,%3}, {%4,%5,%6,%7}, {%8,%9}, {%0,%1,%2,%3};\n"
        : "+f"(c[0]), "+f"(c[1]), "+f"(c[2]), "+f"(c[3])
        : "r"(a[0]), "r"(a[1]), "r"(a[2]), "r"(a[3]), "r"(b[0]), "r"(b[1]));
}

__device__ __forceinline__ void cp16(unsigned* smem_dst, const void* gmem_src) {
    unsigned sa = (unsigned)__cvta_generic_to_shared(smem_dst);
    asm volatile("cp.async.cg.shared.global [%0], [%1], 16;" :: "r"(sa), "l"(gmem_src));
}
#define CP_COMMIT() asm volatile("cp.async.commit_group;")
#define CP_WAIT0()  asm volatile("cp.async.wait_group 0;")

// ---------------------------------------------------------------------------
// Kernel 0: transpose x [b][c][s] -> fp16 tok [b][s][c]
// ---------------------------------------------------------------------------
__global__ __launch_bounds__(256) void transpose_kernel(const float* __restrict__ x)
{
    __shared__ float tile[32][33];
    const int tx = threadIdx.x & 31, ty = threadIdx.x >> 5;  // 32 x 8
    const int s0 = blockIdx.x * 32, c0 = blockIdx.y * 32, b = blockIdx.z;
#pragma unroll
    for (int i = 0; i < 4; i++) {
        const int cl = ty + i * 8;
        tile[cl][tx] = x[((size_t)b * CCH + c0 + cl) * SEQ + s0 + tx];
    }
    __syncthreads();
#pragma unroll
    for (int i = 0; i < 4; i++) {
        const int sl = ty + i * 8;
        g_tok[((size_t)b * SEQ + s0 + sl) * CCH + c0 + tx] = __float2half_rn(tile[tx][sl]);
    }
}

// ---------------------------------------------------------------------------
// Kernel 1: QKV projections (fp16 mma, fp32 accum).  Tile 128(s) x 64(o), k=32.
// ---------------------------------------------------------------------------
__global__ __launch_bounds__(256) void qkv_kernel(
    const float* __restrict__ Wq, const float* __restrict__ bq,
    const float* __restrict__ Wk, const float* __restrict__ bk,
    const float* __restrict__ Wv, const float* __restrict__ bv)
{
    __shared__ unsigned As[128 * 20];  // [s][c]  16 uint data + 4 pad
    __shared__ unsigned Bs[64 * 20];   // [o][c]

    const int t = threadIdx.x;
    const int lane = t & 31, wid = t >> 5;
    const int g = lane >> 2, t4 = lane & 3;
    const int wm = wid & 3, wn = wid >> 2;
    const int s0 = blockIdx.x * 128;
    const int o0 = blockIdx.y * 64;
    const int z  = blockIdx.z;
    const int which = z % 3, b = z / 3;

    const float *W, *bias;
    if (which == 0)      { W = Wq; bias = bq; }
    else if (which == 1) { W = Wk; bias = bk; }
    else                 { W = Wv; bias = bv; }

    const float4* Wf4 = reinterpret_cast<const float4*>(W);

    float acc[2][4][4];
#pragma unroll
    for (int i = 0; i < 2; i++)
#pragma unroll
        for (int j = 0; j < 4; j++)
#pragma unroll
            for (int q = 0; q < 4; q++) acc[i][j][q] = 0.f;

    for (int k0 = 0; k0 < CCH; k0 += 32) {
        // A: tok rows (fp16, straight uint4 copies)
#pragma unroll
        for (int u = 0; u < 2; u++) {
            int idx = t + u * 256;
            int r = idx >> 2, q4 = idx & 3;
            const uint4* src = reinterpret_cast<const uint4*>(
                g_tok + ((size_t)b * SEQ + s0 + r) * CCH + k0);
            *reinterpret_cast<uint4*>(&As[r * 20 + q4 * 4]) = src[q4];
        }
        // B: W fp32 -> fp16 pairs
#pragma unroll
        for (int u = 0; u < 2; u++) {
            int idx = t + u * 256;
            int o = idx >> 3, c4 = idx & 7;
            float4 v = Wf4[(size_t)(o0 + o) * (CCH / 4) + (k0 >> 2) + c4];
            *reinterpret_cast<uint2*>(&Bs[o * 20 + c4 * 2]) =
                make_uint2(pack2(v.x, v.y), pack2(v.z, v.w));
        }
        __syncthreads();

#pragma unroll
        for (int kc = 0; kc < 2; kc++) {
            unsigned a[2][4], bf[4][2];
#pragma unroll
            for (int tm = 0; tm < 2; tm++) {
                const int r = wm * 32 + tm * 16 + g;
                a[tm][0] = As[r * 20 + kc * 8 + t4];
                a[tm][1] = As[(r + 8) * 20 + kc * 8 + t4];
                a[tm][2] = As[r * 20 + kc * 8 + t4 + 4];
                a[tm][3] = As[(r + 8) * 20 + kc * 8 + t4 + 4];
            }
#pragma unroll
            for (int tn = 0; tn < 4; tn++) {
                const int o = wn * 32 + tn * 8 + g;
                bf[tn][0] = Bs[o * 20 + kc * 8 + t4];
                bf[tn][1] = Bs[o * 20 + kc * 8 + t4 + 4];
            }
#pragma unroll
            for (int tm = 0; tm < 2; tm++)
#pragma unroll
                for (int tn = 0; tn < 4; tn++)
                    mma16(acc[tm][tn], a[tm], bf[tn]);
        }
        __syncthreads();
    }

    const int h  = o0 >> 6;
    const int bh = b * NH + h;
#pragma unroll
    for (int tm = 0; tm < 2; tm++) {
#pragma unroll
        for (int tn = 0; tn < 4; tn++) {
            const int col0 = wn * 32 + tn * 8 + 2 * t4;
            const float b0 = bias[o0 + col0];
            const float b1 = bias[o0 + col0 + 1];
#pragma unroll
            for (int half = 0; half < 2; half++) {
                const int s = s0 + wm * 32 + tm * 16 + g + half * 8;
                const float v0 = acc[tm][tn][half * 2 + 0] + b0;
                const float v1 = acc[tm][tn][half * 2 + 1] + b1;
                if (which == 0) {
                    *reinterpret_cast<unsigned*>(
                        &g_q16[((size_t)bh * SEQ + s) * HD + col0]) = pack2(v0, v1);
                } else if (which == 1) {
                    *reinterpret_cast<unsigned*>(
                        &g_k16[((size_t)bh * SEQ + s) * HD + col0]) = pack2(v0, v1);
                } else {
                    g_v16[((size_t)bh * HD + col0) * SEQ + s]     = __float2half_rn(v0);
                    g_v16[((size_t)bh * HD + col0 + 1) * SEQ + s] = __float2half_rn(v1);
                }
            }
        }
    }
}

// ---------------------------------------------------------------------------
// Kernel 2: flash attention, fp16 mma.  128-query tile, 8 warps x 16 rows.
// Q fragments direct from gmem; P stays in registers (C-frag == A-frag layout);
// cp.async double-buffered K/V.  smem = 4 * 64 * 36 * 4 = 36864 B.
// ---------------------------------------------------------------------------
extern __shared__ unsigned fa_sh[];

__global__ void __launch_bounds__(256, 2) flash_kernel()
{
    unsigned* Kb0 = fa_sh;               // [64][36]  Ks[j][d]
    unsigned* Kb1 = Kb0 + 64 * 36;
    unsigned* Vb0 = Kb1 + 64 * 36;       // Vs[dd][j]
    unsigned* Vb1 = Vb0 + 64 * 36;

    const int t = threadIdx.x, lane = t & 31, wid = t >> 5;
    const int g = lane >> 2, t4 = lane & 3;
    const int bh = blockIdx.y, s0 = blockIdx.x * 128;
    const int b = bh >> 3, h = bh & 7;

    const unsigned* qU = reinterpret_cast<const unsigned*>(g_q16 + (size_t)bh * SEQ * HD);
    const __half*   kP = g_k16 + (size_t)bh * SEQ * HD;
    const __half*   vP = g_v16 + (size_t)bh * HD * SEQ;

    // ---- prologue: K0/V0 cp.async + Q fragments from gmem ----
#pragma unroll
    for (int u = 0; u < 2; u++) {
        int idx = t + u * 256;
        int r = idx >> 3, ch = idx & 7;
        cp16(&Kb0[r * 36 + ch * 4], kP + (size_t)r * HD + ch * 8);
        cp16(&Vb0[r * 36 + ch * 4], vP + (size_t)r * SEQ + ch * 8);
    }
    CP_COMMIT();

    const int row = wid * 16 + g;
    unsigned qf[4][4];   // [kc][frag]
#pragma unroll
    for (int kc = 0; kc < 4; kc++) {
        qf[kc][0] = qU[(size_t)(s0 + row) * 32 + kc * 8 + t4];
        qf[kc][1] = qU[(size_t)(s0 + row + 8) * 32 + kc * 8 + t4];
        qf[kc][2] = qU[(size_t)(s0 + row) * 32 + kc * 8 + t4 + 4];
        qf[kc][3] = qU[(size_t)(s0 + row + 8) * 32 + kc * 8 + t4 + 4];
    }

    CP_WAIT0();
    __syncthreads();

    const float SC = 0.125f * 1.44269504088896f;   // 1/sqrt(64) * log2(e)
    float m0 = -1e30f, m1 = -1e30f, l0 = 0.f, l1 = 0.f;
    float oacc[8][4];
#pragma unroll
    for (int i = 0; i < 8; i++)
#pragma unroll
        for (int j = 0; j < 4; j++) oacc[i][j] = 0.f;

    for (int kt = 0; kt < 64; kt++) {
        unsigned* Kc = (kt & 1) ? Kb1 : Kb0;
        unsigned* Vc = (kt & 1) ? Vb1 : Vb0;

        if (kt < 63) {   // background prefetch
            unsigned* Kn = (kt & 1) ? Kb0 : Kb1;
            unsigned* Vn = (kt & 1) ? Vb0 : Vb1;
            const int koff = (kt + 1) * 64;
#pragma unroll
            for (int u = 0; u < 2; u++) {
                int idx = t + u * 256;
                int r = idx >> 3, ch = idx & 7;
                cp16(&Kn[r * 36 + ch * 4], kP + (size_t)(koff + r) * HD + ch * 8);
                cp16(&Vn[r * 36 + ch * 4], vP + (size_t)r * SEQ + koff + ch * 8);
            }
            CP_COMMIT();
        }

        // ---- S = Q K^T ----
        float s_f[8][4];
#pragma unroll
        for (int i = 0; i < 8; i++)
#pragma unroll
            for (int j = 0; j < 4; j++) s_f[i][j] = 0.f;

#pragma unroll
        for (int kc = 0; kc < 4; kc++) {
#pragma unroll
            for (int tn = 0; tn < 8; tn++) {
                unsigned bb[2];
                const int n = tn * 8 + g;
                bb[0] = Kc[n * 36 + kc * 8 + t4];
                bb[1] = Kc[n * 36 + kc * 8 + t4 + 4];
                mma16(s_f[tn], qf[kc], bb);
            }
        }

        // ---- online softmax (exp2 domain) ----
        float mx0 = -1e30f, mx1 = -1e30f;
#pragma unroll
        for (int tn = 0; tn < 8; tn++) {
#pragma unroll
            for (int j = 0; j < 4; j++) s_f[tn][j] *= SC;
            mx0 = fmaxf(mx0, fmaxf(s_f[tn][0], s_f[tn][1]));
            mx1 = fmaxf(mx1, fmaxf(s_f[tn][2], s_f[tn][3]));
        }
        mx0 = fmaxf(mx0, __shfl_xor_sync(0xffffffffu, mx0, 1));
        mx0 = fmaxf(mx0, __shfl_xor_sync(0xffffffffu, mx0, 2));
        mx1 = fmaxf(mx1, __shfl_xor_sync(0xffffffffu, mx1, 1));
        mx1 = fmaxf(mx1, __shfl_xor_sync(0xffffffffu, mx1, 2));

        const float nm0 = fmaxf(m0, mx0), nm1 = fmaxf(m1, mx1);
        const float al0 = exp2f(m0 - nm0), al1 = exp2f(m1 - nm1);
        float ls0 = 0.f, ls1 = 0.f;
#pragma unroll
        for (int tn = 0; tn < 8; tn++) {
            s_f[tn][0] = exp2f(s_f[tn][0] - nm0);
            s_f[tn][1] = exp2f(s_f[tn][1] - nm0);
            s_f[tn][2] = exp2f(s_f[tn][2] - nm1);
            s_f[tn][3] = exp2f(s_f[tn][3] - nm1);
            ls0 += s_f[tn][0] + s_f[tn][1];
            ls1 += s_f[tn][2] + s_f[tn][3];
        }
        ls0 += __shfl_xor_sync(0xffffffffu, ls0, 1);
        ls0 += __shfl_xor_sync(0xffffffffu, ls0, 2);
        ls1 += __shfl_xor_sync(0xffffffffu, ls1, 1);
        ls1 += __shfl_xor_sync(0xffffffffu, ls1, 2);
        l0 = l0 * al0 + ls0;  m0 = nm0;
        l1 = l1 * al1 + ls1;  m1 = nm1;

#pragma unroll
        for (int tn = 0; tn < 8; tn++) {
            oacc[tn][0] *= al0; oacc[tn][1] *= al0;
            oacc[tn][2] *= al1; oacc[tn][3] *= al1;
        }

        // ---- O += P V  (P packed straight from S fragments: C-frag == A-frag) ----
#pragma unroll
        for (int kc = 0; kc < 4; kc++) {
            unsigned a[4];
            a[0] = pack2(s_f[2 * kc][0],     s_f[2 * kc][1]);
            a[1] = pack2(s_f[2 * kc][2],     s_f[2 * kc][3]);
            a[2] = pack2(s_f[2 * kc + 1][0], s_f[2 * kc + 1][1]);
            a[3] = pack2(s_f[2 * kc + 1][2], s_f[2 * kc + 1][3]);
#pragma unroll
            for (int tn = 0; tn < 8; tn++) {
                unsigned bb[2];
                const int n = tn * 8 + g;
                bb[0] = Vc[n * 36 + kc * 8 + t4];
                bb[1] = Vc[n * 36 + kc * 8 + t4 + 4];
                mma16(oacc[tn], a, bb);
            }
        }

        if (kt < 63) {
            CP_WAIT0();
            __syncthreads();
        }
    }

    // ---- epilogue: normalize + fp16 store to [b][s][c] ----
    const float r0 = 1.f / l0, r1 = 1.f / l1;
    const int srow = s0 + row;
#pragma unroll
    for (int tn = 0; tn < 8; tn++) {
        const int c = h * 64 + tn * 8 + 2 * t4;
        *reinterpret_cast<unsigned*>(&g_o16[((size_t)b * SEQ + srow) * CCH + c]) =
            pack2(oacc[tn][0] * r0, oacc[tn][1] * r0);
        *reinterpret_cast<unsigned*>(&g_o16[((size_t)b * SEQ + srow + 8) * CCH + c]) =
            pack2(oacc[tn][2] * r1, oacc[tn][3] * r1);
    }
}

// ---------------------------------------------------------------------------
// Kernel 3: out-projection (fp16 mma) + fp32 transposed store to [b][c][h][w].
// ---------------------------------------------------------------------------
__global__ __launch_bounds__(256) void proj_kernel(
    const float* __restrict__ Wp, const float* __restrict__ bp,
    float* __restrict__ out)
{
    __shared__ unsigned As[128 * 20];  // [s][c]
    __shared__ unsigned Bs[64 * 20];   // [o][c]

    const int t = threadIdx.x;
    const int lane = t & 31, wid = t >> 5;
    const int g = lane >> 2, t4 = lane & 3;
    const int wm = wid & 3, wn = wid >> 2;
    const int s0 = blockIdx.x * 128;
    const int o0 = blockIdx.y * 64;
    const int b  = blockIdx.z;

    const float4* Wf4 = reinterpret_cast<const float4*>(Wp);

    float acc[2][4][4];
#pragma unroll
    for (int i = 0; i < 2; i++)
#pragma unroll
        for (int j = 0; j < 4; j++)
#pragma unroll
            for (int q = 0; q < 4; q++) acc[i][j][q] = 0.f;

    for (int k0 = 0; k0 < CCH; k0 += 32) {
#pragma unroll
        for (int u = 0; u < 2; u++) {
            int idx = t + u * 256;
            int r = idx >> 2, q4 = idx & 3;
            const uint4* src = reinterpret_cast<const uint4*>(
                g_o16 + ((size_t)b * SEQ + s0 + r) * CCH + k0);
            *reinterpret_cast<uint4*>(&As[r * 20 + q4 * 4]) = src[q4];
        }
#pragma unroll
        for (int u = 0; u < 2; u++) {
            int idx = t + u * 256;
            int o = idx >> 3, c4 = idx & 7;
            float4 v = Wf4[(size_t)(o0 + o) * (CCH / 4) + (k0 >> 2) + c4];
            *reinterpret_cast<uint2*>(&Bs[o * 20 + c4 * 2]) =
                make_uint2(pack2(v.x, v.y), pack2(v.z, v.w));
        }
        __syncthreads();

#pragma unroll
        for (int kc = 0; kc < 2; kc++) {
            unsigned a[2][4], bf[4][2];
#pragma unroll
            for (int tm = 0; tm < 2; tm++) {
                const int r = wm * 32 + tm * 16 + g;
                a[tm][0] = As[r * 20 + kc * 8 + t4];
                a[tm][1] = As[(r + 8) * 20 + kc * 8 + t4];
                a[tm][2] = As[r * 20 + kc * 8 + t4 + 4];
                a[tm][3] = As[(r + 8) * 20 + kc * 8 + t4 + 4];
            }
#pragma unroll
            for (int tn = 0; tn < 4; tn++) {
                const int o = wn * 32 + tn * 8 + g;
                bf[tn][0] = Bs[o * 20 + kc * 8 + t4];
                bf[tn][1] = Bs[o * 20 + kc * 8 + t4 + 4];
            }
#pragma unroll
            for (int tm = 0; tm < 2; tm++)
#pragma unroll
                for (int tn = 0; tn < 4; tn++)
                    mma16(acc[tm][tn], a[tm], bf[tn]);
        }
        __syncthreads();
    }

#pragma unroll
    for (int tm = 0; tm < 2; tm++) {
#pragma unroll
        for (int tn = 0; tn < 4; tn++) {
            const int col0 = o0 + wn * 32 + tn * 8 + 2 * t4;
            const float b0 = bp[col0], b1 = bp[col0 + 1];
#pragma unroll
            for (int half = 0; half < 2; half++) {
                const int s = s0 + wm * 32 + tm * 16 + g + half * 8;
                out[((size_t)b * CCH + col0) * SEQ + s]     = acc[tm][tn][half * 2 + 0] + b0;
                out[((size_t)b * CCH + col0 + 1) * SEQ + s] = acc[tm][tn][half * 2 + 1] + b1;
            }
        }
    }
}

// ---------------------------------------------------------------------------
extern "C" void kernel_launch(void* const* d_in, const int* in_sizes, int n_in,
                              void* d_out, int out_size)
{
    const float* x  = (const float*)d_in[0];
    const float* Wq = (const float*)d_in[1];
    const float* bq = (const float*)d_in[2];
    const float* Wk = (const float*)d_in[3];
    const float* bk = (const float*)d_in[4];
    const float* Wv = (const float*)d_in[5];
    const float* bv = (const float*)d_in[6];
    const float* Wp = (const float*)d_in[7];
    const float* bp = (const float*)d_in[8];
    float* out = (float*)d_out;

    const int FA_SMEM = 4 * 64 * 36 * 4;  // 36864 B
    cudaFuncSetAttribute(flash_kernel,
                         cudaFuncAttributeMaxDynamicSharedMemorySize, FA_SMEM);

    transpose_kernel<<<dim3(SEQ / 32, CCH / 32, BATCH), 256>>>(x);
    qkv_kernel<<<dim3(SEQ / 128, CCH / 64, 3 * BATCH), 256>>>(
        Wq, bq, Wk, bk, Wv, bv);
    flash_kernel<<<dim3(SEQ / 128, BH), 256, FA_SMEM>>>();
    proj_kernel<<<dim3(SEQ / 128, CCH / 64, BATCH), 256>>>(Wp, bp, out);
}

// round 6
// speedup vs baseline: 7.7804x; 1.1192x over previous
#include <cuda_runtime.h>
#include <cuda_fp16.h>
#include <math.h>

#define BATCH 2
#define CCH   512
#define SEQ   4096
#define NH    8
#define HD    64
#define BH    (BATCH*NH)

// fp16 scratch (allocation-free device globals)
__device__ __half g_tok[(size_t)BATCH * SEQ * CCH]; // [b][s][c]
__device__ __half g_q16[(size_t)BH * SEQ * HD];     // [bh][s][d]  (pre-scaled by 0.125*log2e)
__device__ __half g_k16[(size_t)BH * SEQ * HD];     // [bh][s][d]
__device__ __half g_v16[(size_t)BH * HD * SEQ];     // [bh][d][s]
__device__ __half g_o16[(size_t)BATCH * SEQ * CCH]; // [b][s][c]

__device__ __forceinline__ unsigned pack2(float lo, float hi) {
    __half2 h = __floats2half2_rn(lo, hi);
    return *reinterpret_cast<unsigned*>(&h);
}

// exp2 of two fp32 values, result packed fp16x2 (single MUFU op)
__device__ __forceinline__ unsigned ex2h2(float lo, float hi) {
    unsigned p = pack2(lo, hi), r;
    asm("ex2.approx.f16x2 %0, %1;" : "=r"(r) : "r"(p));
    return r;
}

__device__ __forceinline__ void mma16(float c[4], const unsigned a[4], const unsigned b[2]) {
    asm volatile(
        "mma.sync.aligned.m16n8k16.row.col.f32.f16.f16.f32 "
        "{%0,%1,%2,%3}, {%4,%5,%6,%7}, {%8,%9}, {%0,%1,%2,%3};\n"
        : "+f"(c[0]), "+f"(c[1]), "+f"(c[2]), "+f"(c[3])
        : "r"(a[0]), "r"(a[1]), "r"(a[2]), "r"(a[3]), "r"(b[0]), "r"(b[1]));
}

__device__ __forceinline__ void ldsm4(unsigned& r0, unsigned& r1, unsigned& r2, unsigned& r3,
                                      unsigned addr) {
    asm volatile("ldmatrix.sync.aligned.m8n8.x4.shared.b16 {%0,%1,%2,%3}, [%4];"
                 : "=r"(r0), "=r"(r1), "=r"(r2), "=r"(r3) : "r"(addr));
}

__device__ __forceinline__ void cp16(unsigned* smem_dst, const void* gmem_src) {
    unsigned sa = (unsigned)__cvta_generic_to_shared(smem_dst);
    asm volatile("cp.async.cg.shared.global [%0], [%1], 16;" :: "r"(sa), "l"(gmem_src));
}
#define CP_COMMIT() asm volatile("cp.async.commit_group;")
#define CP_WAIT0()  asm volatile("cp.async.wait_group 0;")

// ---------------------------------------------------------------------------
// Kernel 0: transpose x [b][c][s] -> fp16 tok [b][s][c]
// ---------------------------------------------------------------------------
__global__ __launch_bounds__(256) void transpose_kernel(const float* __restrict__ x)
{
    __shared__ float tile[32][33];
    const int tx = threadIdx.x & 31, ty = threadIdx.x >> 5;
    const int s0 = blockIdx.x * 32, c0 = blockIdx.y * 32, b = blockIdx.z;
#pragma unroll
    for (int i = 0; i < 4; i++) {
        const int cl = ty + i * 8;
        tile[cl][tx] = x[((size_t)b * CCH + c0 + cl) * SEQ + s0 + tx];
    }
    __syncthreads();
#pragma unroll
    for (int i = 0; i < 4; i++) {
        const int sl = ty + i * 8;
        g_tok[((size_t)b * SEQ + s0 + sl) * CCH + c0 + tx] = __float2half_rn(tile[tx][sl]);
    }
}

// ---------------------------------------------------------------------------
// Kernel 1: QKV projections.  Tile 128(s) x 128(o), k=32 chunks.
// Warps 4(m) x 2(n): each 32 rows x 64 cols -> acc[2][8][4].
// Q is written pre-scaled by 0.125*log2(e).
// ---------------------------------------------------------------------------
__global__ __launch_bounds__(256) void qkv_kernel(
    const float* __restrict__ Wq, const float* __restrict__ bq,
    const float* __restrict__ Wk, const float* __restrict__ bk,
    const float* __restrict__ Wv, const float* __restrict__ bv)
{
    __shared__ unsigned As[128 * 20];  // [s][c] 16 data uint + 4 pad
    __shared__ unsigned Bs[128 * 20];  // [o][c]

    const int t = threadIdx.x;
    const int lane = t & 31, wid = t >> 5;
    const int g = lane >> 2, t4 = lane & 3;
    const int wm = wid & 3, wn = wid >> 2;   // wn 0..1
    const int s0 = blockIdx.x * 128;
    const int o0 = blockIdx.y * 128;
    const int z  = blockIdx.z;
    const int which = z % 3, b = z / 3;

    const float *W, *bias;
    if (which == 0)      { W = Wq; bias = bq; }
    else if (which == 1) { W = Wk; bias = bk; }
    else                 { W = Wv; bias = bv; }

    const float4* Wf4 = reinterpret_cast<const float4*>(W);

    float acc[2][8][4];
#pragma unroll
    for (int i = 0; i < 2; i++)
#pragma unroll
        for (int j = 0; j < 8; j++)
#pragma unroll
            for (int q = 0; q < 4; q++) acc[i][j][q] = 0.f;

    for (int k0 = 0; k0 < CCH; k0 += 32) {
        // A: fp16 tok rows, straight uint4 copies
#pragma unroll
        for (int u = 0; u < 2; u++) {
            int idx = t + u * 256;
            int r = idx >> 2, q4 = idx & 3;
            const uint4* src = reinterpret_cast<const uint4*>(
                g_tok + ((size_t)b * SEQ + s0 + r) * CCH + k0);
            *reinterpret_cast<uint4*>(&As[r * 20 + q4 * 4]) = src[q4];
        }
        // B: W rows fp32 -> fp16
#pragma unroll
        for (int u = 0; u < 2; u++) {
            int idx = t + u * 256;
            int o = idx >> 2, q4 = idx & 3;
            float4 va = Wf4[(size_t)(o0 + o) * (CCH / 4) + (k0 >> 2) + q4 * 2];
            float4 vb = Wf4[(size_t)(o0 + o) * (CCH / 4) + (k0 >> 2) + q4 * 2 + 1];
            *reinterpret_cast<uint4*>(&Bs[o * 20 + q4 * 4]) =
                make_uint4(pack2(va.x, va.y), pack2(va.z, va.w),
                           pack2(vb.x, vb.y), pack2(vb.z, vb.w));
        }
        __syncthreads();

#pragma unroll
        for (int kc = 0; kc < 2; kc++) {
            unsigned a[2][4];
#pragma unroll
            for (int tm = 0; tm < 2; tm++) {
                const int r = wm * 32 + tm * 16 + g;
                a[tm][0] = As[r * 20 + kc * 8 + t4];
                a[tm][1] = As[(r + 8) * 20 + kc * 8 + t4];
                a[tm][2] = As[r * 20 + kc * 8 + t4 + 4];
                a[tm][3] = As[(r + 8) * 20 + kc * 8 + t4 + 4];
            }
#pragma unroll
            for (int tn = 0; tn < 8; tn++) {
                unsigned bf[2];
                const int o = wn * 64 + tn * 8 + g;
                bf[0] = Bs[o * 20 + kc * 8 + t4];
                bf[1] = Bs[o * 20 + kc * 8 + t4 + 4];
#pragma unroll
                for (int tm = 0; tm < 2; tm++)
                    mma16(acc[tm][tn], a[tm], bf);
            }
        }
        __syncthreads();
    }

    const float QSC = 0.125f * 1.44269504088896f;
#pragma unroll
    for (int tm = 0; tm < 2; tm++) {
#pragma unroll
        for (int tn = 0; tn < 8; tn++) {
            const int cg = o0 + wn * 64 + tn * 8 + 2 * t4;   // global out channel
            const int h  = cg >> 6;
            const int d  = cg & 63;
            const int bh = b * NH + h;
            const float b0 = bias[cg], b1 = bias[cg + 1];
#pragma unroll
            for (int half = 0; half < 2; half++) {
                const int s = s0 + wm * 32 + tm * 16 + g + half * 8;
                float v0 = acc[tm][tn][half * 2 + 0] + b0;
                float v1 = acc[tm][tn][half * 2 + 1] + b1;
                if (which == 0) {
                    v0 *= QSC; v1 *= QSC;
                    *reinterpret_cast<unsigned*>(
                        &g_q16[((size_t)bh * SEQ + s) * HD + d]) = pack2(v0, v1);
                } else if (which == 1) {
                    *reinterpret_cast<unsigned*>(
                        &g_k16[((size_t)bh * SEQ + s) * HD + d]) = pack2(v0, v1);
                } else {
                    g_v16[((size_t)bh * HD + d) * SEQ + s]     = __float2half_rn(v0);
                    g_v16[((size_t)bh * HD + d + 1) * SEQ + s] = __float2half_rn(v1);
                }
            }
        }
    }
}

// ---------------------------------------------------------------------------
// Kernel 2: flash attention.  128-query tile, 8 warps x 16 rows, 64-key iters.
// ldmatrix B-frags; half2 exp; l accumulated via ones-column mma.
// smem = 4 * 64 * 36 * 4 = 36864 B.
// ---------------------------------------------------------------------------
extern __shared__ unsigned fa_sh[];

__global__ void __launch_bounds__(256, 2) flash_kernel()
{
    unsigned* Kb0 = fa_sh;               // [64][36]  K[j][d]
    unsigned* Kb1 = Kb0 + 64 * 36;
    unsigned* Vb0 = Kb1 + 64 * 36;       // V[dd][j]
    unsigned* Vb1 = Vb0 + 64 * 36;

    const int t = threadIdx.x, lane = t & 31, wid = t >> 5;
    const int g = lane >> 2, t4 = lane & 3;
    const int bh = blockIdx.y, s0 = blockIdx.x * 128;
    const int b = bh >> 3, h = bh & 7;

    const unsigned* qU = reinterpret_cast<const unsigned*>(g_q16 + (size_t)bh * SEQ * HD);
    const __half*   kP = g_k16 + (size_t)bh * SEQ * HD;
    const __half*   vP = g_v16 + (size_t)bh * HD * SEQ;

    // ---- prologue: K0/V0 cp.async ----
#pragma unroll
    for (int u = 0; u < 2; u++) {
        int idx = t + u * 256;
        int r = idx >> 3, ch = idx & 7;
        cp16(&Kb0[r * 36 + ch * 4], kP + (size_t)r * HD + ch * 8);
        cp16(&Vb0[r * 36 + ch * 4], vP + (size_t)r * SEQ + ch * 8);
    }
    CP_COMMIT();

    // Q fragments from gmem (already scaled)
    const int row = wid * 16 + g;
    unsigned qf[4][4];
#pragma unroll
    for (int kc = 0; kc < 4; kc++) {
        qf[kc][0] = qU[(size_t)(s0 + row) * 32 + kc * 8 + t4];
        qf[kc][1] = qU[(size_t)(s0 + row + 8) * 32 + kc * 8 + t4];
        qf[kc][2] = qU[(size_t)(s0 + row) * 32 + kc * 8 + t4 + 4];
        qf[kc][3] = qU[(size_t)(s0 + row + 8) * 32 + kc * 8 + t4 + 4];
    }

    // ldmatrix lane base addresses
    const int grp = lane >> 3, r8 = lane & 7;
    const int nrow = r8 + ((grp & 2) ? 8 : 0);
    const unsigned koff = (grp & 1) ? 16u : 0u;       // bytes
    const unsigned sbase = (unsigned)__cvta_generic_to_shared(fa_sh);
    const unsigned BUF = 64 * 36 * 4;
    unsigned kA[2], vA[2];
    kA[0] = sbase + nrow * 144 + koff;
    kA[1] = kA[0] + BUF;
    vA[0] = kA[0] + 2 * BUF;
    vA[1] = kA[0] + 3 * BUF;

    // ones B-frag for the l-column (col n=0 of a virtual V row of ones)
    unsigned bbl[2];
    bbl[0] = bbl[1] = (g == 0) ? 0x3C003C00u : 0u;

    CP_WAIT0();
    __syncthreads();

    float m0 = -1e30f, m1 = -1e30f;
    float oacc[8][4], lacc[4];
#pragma unroll
    for (int i = 0; i < 8; i++)
#pragma unroll
        for (int j = 0; j < 4; j++) oacc[i][j] = 0.f;
#pragma unroll
    for (int j = 0; j < 4; j++) lacc[j] = 0.f;

    for (int kt = 0; kt < 64; kt++) {
        const unsigned kBase = kA[kt & 1], vBase = vA[kt & 1];

        if (kt < 63) {   // background prefetch into other buffer
            unsigned* Kn = (kt & 1) ? Kb0 : Kb1;
            unsigned* Vn = (kt & 1) ? Vb0 : Vb1;
            const int koff2 = (kt + 1) * 64;
#pragma unroll
            for (int u = 0; u < 2; u++) {
                int idx = t + u * 256;
                int r = idx >> 3, ch = idx & 7;
                cp16(&Kn[r * 36 + ch * 4], kP + (size_t)(koff2 + r) * HD + ch * 8);
                cp16(&Vn[r * 36 + ch * 4], vP + (size_t)r * SEQ + koff2 + ch * 8);
            }
            CP_COMMIT();
        }

        // ---- S = Q K^T (pre-scaled, log2 domain) ----
        float s_f[8][4];
#pragma unroll
        for (int i = 0; i < 8; i++)
#pragma unroll
            for (int j = 0; j < 4; j++) s_f[i][j] = 0.f;

#pragma unroll
        for (int kc = 0; kc < 4; kc++) {
#pragma unroll
            for (int p = 0; p < 4; p++) {
                unsigned b0, b1, b2, b3;
                ldsm4(b0, b1, b2, b3, kBase + p * 2304 + kc * 32);
                unsigned bb0[2] = {b0, b1}, bb1[2] = {b2, b3};
                mma16(s_f[2 * p],     qf[kc], bb0);
                mma16(s_f[2 * p + 1], qf[kc], bb1);
            }
        }

        // ---- online softmax ----
        float mx0 = -1e30f, mx1 = -1e30f;
#pragma unroll
        for (int tn = 0; tn < 8; tn++) {
            mx0 = fmaxf(mx0, fmaxf(s_f[tn][0], s_f[tn][1]));
            mx1 = fmaxf(mx1, fmaxf(s_f[tn][2], s_f[tn][3]));
        }
        mx0 = fmaxf(mx0, __shfl_xor_sync(0xffffffffu, mx0, 1));
        mx0 = fmaxf(mx0, __shfl_xor_sync(0xffffffffu, mx0, 2));
        mx1 = fmaxf(mx1, __shfl_xor_sync(0xffffffffu, mx1, 1));
        mx1 = fmaxf(mx1, __shfl_xor_sync(0xffffffffu, mx1, 2));

        const float nm0 = fmaxf(m0, mx0), nm1 = fmaxf(m1, mx1);
        const float al0 = exp2f(m0 - nm0), al1 = exp2f(m1 - nm1);
        m0 = nm0; m1 = nm1;

        unsigned e01[8], e23[8];
#pragma unroll
        for (int tn = 0; tn < 8; tn++) {
            e01[tn] = ex2h2(s_f[tn][0] - nm0, s_f[tn][1] - nm0);
            e23[tn] = ex2h2(s_f[tn][2] - nm1, s_f[tn][3] - nm1);
        }

#pragma unroll
        for (int tn = 0; tn < 8; tn++) {
            oacc[tn][0] *= al0; oacc[tn][1] *= al0;
            oacc[tn][2] *= al1; oacc[tn][3] *= al1;
        }
        lacc[0] *= al0; lacc[2] *= al1;

        // ---- O += P V ;  l += P 1  ----
#pragma unroll
        for (int kc = 0; kc < 4; kc++) {
            unsigned a[4];
            a[0] = e01[2 * kc];     a[1] = e23[2 * kc];
            a[2] = e01[2 * kc + 1]; a[3] = e23[2 * kc + 1];
#pragma unroll
            for (int p = 0; p < 4; p++) {
                unsigned b0, b1, b2, b3;
                ldsm4(b0, b1, b2, b3, vBase + p * 2304 + kc * 32);
                unsigned bb0[2] = {b0, b1}, bb1[2] = {b2, b3};
                mma16(oacc[2 * p],     a, bb0);
                mma16(oacc[2 * p + 1], a, bb1);
            }
            mma16(lacc, a, bbl);
        }

        if (kt < 63) {
            CP_WAIT0();
            __syncthreads();
        }
    }

    // ---- epilogue ----
    const float l0 = __shfl_sync(0xffffffffu, lacc[0], lane & 28);
    const float l1 = __shfl_sync(0xffffffffu, lacc[2], lane & 28);
    const float r0 = 1.f / l0, r1 = 1.f / l1;
    const int srow = s0 + row;
#pragma unroll
    for (int tn = 0; tn < 8; tn++) {
        const int c = h * 64 + tn * 8 + 2 * t4;
        *reinterpret_cast<unsigned*>(&g_o16[((size_t)b * SEQ + srow) * CCH + c]) =
            pack2(oacc[tn][0] * r0, oacc[tn][1] * r0);
        *reinterpret_cast<unsigned*>(&g_o16[((size_t)b * SEQ + srow + 8) * CCH + c]) =
            pack2(oacc[tn][2] * r1, oacc[tn][3] * r1);
    }
}

// ---------------------------------------------------------------------------
// Kernel 3: out-projection.  Tile 128(s) x 128(o); fp32 store to [b][c][h][w].
// ---------------------------------------------------------------------------
__global__ __launch_bounds__(256) void proj_kernel(
    const float* __restrict__ Wp, const float* __restrict__ bp,
    float* __restrict__ out)
{
    __shared__ unsigned As[128 * 20];
    __shared__ unsigned Bs[128 * 20];

    const int t = threadIdx.x;
    const int lane = t & 31, wid = t >> 5;
    const int g = lane >> 2, t4 = lane & 3;
    const int wm = wid & 3, wn = wid >> 2;
    const int s0 = blockIdx.x * 128;
    const int o0 = blockIdx.y * 128;
    const int b  = blockIdx.z;

    const float4* Wf4 = reinterpret_cast<const float4*>(Wp);

    float acc[2][8][4];
#pragma unroll
    for (int i = 0; i < 2; i++)
#pragma unroll
        for (int j = 0; j < 8; j++)
#pragma unroll
            for (int q = 0; q < 4; q++) acc[i][j][q] = 0.f;

    for (int k0 = 0; k0 < CCH; k0 += 32) {
#pragma unroll
        for (int u = 0; u < 2; u++) {
            int idx = t + u * 256;
            int r = idx >> 2, q4 = idx & 3;
            const uint4* src = reinterpret_cast<const uint4*>(
                g_o16 + ((size_t)b * SEQ + s0 + r) * CCH + k0);
            *reinterpret_cast<uint4*>(&As[r * 20 + q4 * 4]) = src[q4];
        }
#pragma unroll
        for (int u = 0; u < 2; u++) {
            int idx = t + u * 256;
            int o = idx >> 2, q4 = idx & 3;
            float4 va = Wf4[(size_t)(o0 + o) * (CCH / 4) + (k0 >> 2) + q4 * 2];
            float4 vb = Wf4[(size_t)(o0 + o) * (CCH / 4) + (k0 >> 2) + q4 * 2 + 1];
            *reinterpret_cast<uint4*>(&Bs[o * 20 + q4 * 4]) =
                make_uint4(pack2(va.x, va.y), pack2(va.z, va.w),
                           pack2(vb.x, vb.y), pack2(vb.z, vb.w));
        }
        __syncthreads();

#pragma unroll
        for (int kc = 0; kc < 2; kc++) {
            unsigned a[2][4];
#pragma unroll
            for (int tm = 0; tm < 2; tm++) {
                const int r = wm * 32 + tm * 16 + g;
                a[tm][0] = As[r * 20 + kc * 8 + t4];
                a[tm][1] = As[(r + 8) * 20 + kc * 8 + t4];
                a[tm][2] = As[r * 20 + kc * 8 + t4 + 4];
                a[tm][3] = As[(r + 8) * 20 + kc * 8 + t4 + 4];
            }
#pragma unroll
            for (int tn = 0; tn < 8; tn++) {
                unsigned bf[2];
                const int o = wn * 64 + tn * 8 + g;
                bf[0] = Bs[o * 20 + kc * 8 + t4];
                bf[1] = Bs[o * 20 + kc * 8 + t4 + 4];
#pragma unroll
                for (int tm = 0; tm < 2; tm++)
                    mma16(acc[tm][tn], a[tm], bf);
            }
        }
        __syncthreads();
    }

#pragma unroll
    for (int tm = 0; tm < 2; tm++) {
#pragma unroll
        for (int tn = 0; tn < 8; tn++) {
            const int col0 = o0 + wn * 64 + tn * 8 + 2 * t4;
            const float b0 = bp[col0], b1 = bp[col0 + 1];
#pragma unroll
            for (int half = 0; half < 2; half++) {
                const int s = s0 + wm * 32 + tm * 16 + g + half * 8;
                out[((size_t)b * CCH + col0) * SEQ + s]     = acc[tm][tn][half * 2 + 0] + b0;
                out[((size_t)b * CCH + col0 + 1) * SEQ + s] = acc[tm][tn][half * 2 + 1] + b1;
            }
        }
    }
}

// ---------------------------------------------------------------------------
extern "C" void kernel_launch(void* const* d_in, const int* in_sizes, int n_in,
                              void* d_out, int out_size)
{
    const float* x  = (const float*)d_in[0];
    const float* Wq = (const float*)d_in[1];
    const float* bq = (const float*)d_in[2];
    const float* Wk = (const float*)d_in[3];
    const float* bk = (const float*)d_in[4];
    const float* Wv = (const float*)d_in[5];
    const float* bv = (const float*)d_in[6];
    const float* Wp = (const float*)d_in[7];
    const float* bp = (const float*)d_in[8];
    float* out = (float*)d_out;

    const int FA_SMEM = 4 * 64 * 36 * 4;  // 36864 B
    cudaFuncSetAttribute(flash_kernel,
                         cudaFuncAttributeMaxDynamicSharedMemorySize, FA_SMEM);

    transpose_kernel<<<dim3(SEQ / 32, CCH / 32, BATCH), 256>>>(x);
    qkv_kernel<<<dim3(SEQ / 128, CCH / 128, 3 * BATCH), 256>>>(
        Wq, bq, Wk, bk, Wv, bv);
    flash_kernel<<<dim3(SEQ / 128, BH), 256, FA_SMEM>>>();
    proj_kernel<<<dim3(SEQ / 128, CCH / 128, BATCH), 256>>>(Wp, bp, out);
}

// round 8
// speedup vs baseline: 8.4445x; 1.0854x over previous
#include <cuda_runtime.h>
#include <cuda_fp16.h>
#include <math.h>

#define BATCH 2
#define CCH   512
#define SEQ   4096
#define NH    8
#define HD    64
#define BH    (BATCH*NH)
#define WSZ   (CCH*CCH)

// fp16 scratch (allocation-free device globals)
__device__ __half g_tok[(size_t)BATCH * SEQ * CCH]; // [b][s][c]
__device__ __half g_w16[(size_t)4 * WSZ];           // Wq,Wk,Wv,Wp fp16 [o][c]
__device__ __half g_q16[(size_t)BH * SEQ * HD];     // [bh][s][d] (pre-scaled 0.125*log2e)
__device__ __half g_k16[(size_t)BH * SEQ * HD];     // [bh][s][d]
__device__ __half g_v16[(size_t)BH * HD * SEQ];     // [bh][d][s]
__device__ __half g_o16[(size_t)BATCH * SEQ * CCH]; // [b][s][c]

__device__ __forceinline__ unsigned pack2(float lo, float hi) {
    __half2 h = __floats2half2_rn(lo, hi);
    return *reinterpret_cast<unsigned*>(&h);
}
__device__ __forceinline__ unsigned ex2h2(float lo, float hi) {
    unsigned p = pack2(lo, hi), r;
    asm("ex2.approx.f16x2 %0, %1;" : "=r"(r) : "r"(p));
    return r;
}
__device__ __forceinline__ void mma16(float c[4], const unsigned a[4], const unsigned b[2]) {
    asm volatile(
        "mma.sync.aligned.m16n8k16.row.col.f32.f16.f16.f32 "
        "{%0,%1,%2,%3}, {%4,%5,%6,%7}, {%8,%9}, {%0,%1,%2,%3};\n"
        : "+f"(c[0]), "+f"(c[1]), "+f"(c[2]), "+f"(c[3])
        : "r"(a[0]), "r"(a[1]), "r"(a[2]), "r"(a[3]), "r"(b[0]), "r"(b[1]));
}
__device__ __forceinline__ void ldsm4(unsigned& r0, unsigned& r1, unsigned& r2, unsigned& r3,
                                      unsigned addr) {
    asm volatile("ldmatrix.sync.aligned.m8n8.x4.shared.b16 {%0,%1,%2,%3}, [%4];"
                 : "=r"(r0), "=r"(r1), "=r"(r2), "=r"(r3) : "r"(addr));
}
__device__ __forceinline__ void cp16(unsigned* smem_dst, const void* gmem_src) {
    unsigned sa = (unsigned)__cvta_generic_to_shared(smem_dst);
    asm volatile("cp.async.cg.shared.global [%0], [%1], 16;" :: "r"(sa), "l"(gmem_src));
}
#define CP_COMMIT() asm volatile("cp.async.commit_group;")
#define CP_WAIT0()  asm volatile("cp.async.wait_group 0;")

// ---------------------------------------------------------------------------
// Kernel 0a: transpose x [b][c][s] -> fp16 tok [b][s][c]
// ---------------------------------------------------------------------------
__global__ __launch_bounds__(256) void transpose_kernel(const float* __restrict__ x)
{
    __shared__ float tile[32][33];
    const int tx = threadIdx.x & 31, ty = threadIdx.x >> 5;
    const int s0 = blockIdx.x * 32, c0 = blockIdx.y * 32, b = blockIdx.z;
#pragma unroll
    for (int i = 0; i < 4; i++) {
        const int cl = ty + i * 8;
        tile[cl][tx] = x[((size_t)b * CCH + c0 + cl) * SEQ + s0 + tx];
    }
    __syncthreads();
#pragma unroll
    for (int i = 0; i < 4; i++) {
        const int sl = ty + i * 8;
        g_tok[((size_t)b * SEQ + s0 + sl) * CCH + c0 + tx] = __float2half_rn(tile[tx][sl]);
    }
}

// ---------------------------------------------------------------------------
// Kernel 0b: convert 4 weight matrices fp32 -> fp16 (row-major [o][c])
// ---------------------------------------------------------------------------
__global__ __launch_bounds__(256) void wconv_kernel(
    const float* __restrict__ Wq, const float* __restrict__ Wk,
    const float* __restrict__ Wv, const float* __restrict__ Wp)
{
    const int idx = blockIdx.x * 256 + threadIdx.x;   // grid 1024 -> 262144 threads? no:
    // each thread converts 4 floats; 4*WSZ = 1048576 elems -> 262144 threads
    const float* srcs[4] = {Wq, Wk, Wv, Wp};
    const int mi = idx >> 16;                 // 65536 float4-groups per matrix
    const int off = (idx & 65535) * 4;
    float4 v = *reinterpret_cast<const float4*>(srcs[mi] + off);
    *reinterpret_cast<uint2*>(&g_w16[(size_t)mi * WSZ + off]) =
        make_uint2(pack2(v.x, v.y), pack2(v.z, v.w));
}

// ---------------------------------------------------------------------------
// Kernel 1: QKV projections.  Tile 128(s) x 128(o), k=32, cp.async double buf,
// ldmatrix fragments.  Q written pre-scaled by 0.125*log2(e).
// ---------------------------------------------------------------------------
__shared__ unsigned qkv_sm[10240];   // As0|Bs0|As1|Bs1, each 128*20

__device__ __forceinline__ void stage_tile(unsigned* smA, unsigned* smB,
                                           const __half* aRow, const __half* bRow,
                                           int t, int k0)
{
#pragma unroll
    for (int u = 0; u < 2; u++) {
        int idx = t + u * 256;
        int r = idx >> 2, q4 = idx & 3;
        cp16(&smA[r * 20 + q4 * 4], aRow + (size_t)r * CCH + k0 + q4 * 8);
        cp16(&smB[r * 20 + q4 * 4], bRow + (size_t)r * CCH + k0 + q4 * 8);
    }
}

__global__ __launch_bounds__(256) void qkv_kernel(
    const float* __restrict__ bq, const float* __restrict__ bk,
    const float* __restrict__ bv)
{
    const int t = threadIdx.x;
    const int lane = t & 31, wid = t >> 5;
    const int g = lane >> 2, t4 = lane & 3;
    const int wm = wid & 3, wn = wid >> 2;
    const int s0 = blockIdx.x * 128;
    const int o0 = blockIdx.y * 128;
    const int z  = blockIdx.z;
    const int which = z % 3, b = z / 3;

    const float* bias = (which == 0) ? bq : (which == 1) ? bk : bv;
    const __half* aBase = g_tok + (size_t)b * SEQ * CCH + (size_t)s0 * CCH;
    const __half* bBase = g_w16 + (size_t)which * WSZ + (size_t)o0 * CCH;

    // ldmatrix lane addressing
    const int grp = lane >> 3, r8 = lane & 7;
    const unsigned sbase = (unsigned)__cvta_generic_to_shared(qkv_sm);
    // A: row = mrow + (grp&1)*8 + r8 ; koff = (grp&2)?16:0
    const int aRowAdd = ((grp & 1) << 3) + r8;
    const unsigned aKoff = (grp & 2) ? 16u : 0u;
    // B: row = nbase + (grp&2?8:0) + r8 ; koff = (grp&1)?16:0
    const int bRowAdd = ((grp & 2) << 2) + r8;
    const unsigned bKoff = (grp & 1) ? 16u : 0u;

    float acc[2][8][4];
#pragma unroll
    for (int i = 0; i < 2; i++)
#pragma unroll
        for (int j = 0; j < 8; j++)
#pragma unroll
            for (int q = 0; q < 4; q++) acc[i][j][q] = 0.f;

    stage_tile(qkv_sm, qkv_sm + 2560, aBase, bBase, t, 0);
    CP_COMMIT();

    for (int kt = 0; kt < 16; kt++) {
        CP_WAIT0();
        __syncthreads();
        const int buf = kt & 1;
        if (kt < 15) {
            const int nbuf = (kt + 1) & 1;
            stage_tile(qkv_sm + nbuf * 5120, qkv_sm + nbuf * 5120 + 2560,
                       aBase, bBase, t, (kt + 1) * 32);
            CP_COMMIT();
        }
        const unsigned aB = sbase + (buf * 5120) * 4;
        const unsigned bB = sbase + (buf * 5120 + 2560) * 4;

#pragma unroll
        for (int kc = 0; kc < 2; kc++) {
            unsigned a[2][4];
#pragma unroll
            for (int tm = 0; tm < 2; tm++) {
                const int mrow = wm * 32 + tm * 16;
                ldsm4(a[tm][0], a[tm][1], a[tm][2], a[tm][3],
                      aB + (unsigned)(mrow + aRowAdd) * 80 + aKoff + kc * 32);
            }
#pragma unroll
            for (int p = 0; p < 4; p++) {
                unsigned b0, b1, b2, b3;
                const int nrow = wn * 64 + p * 16;
                ldsm4(b0, b1, b2, b3,
                      bB + (unsigned)(nrow + bRowAdd) * 80 + bKoff + kc * 32);
                unsigned bb0[2] = {b0, b1}, bb1[2] = {b2, b3};
#pragma unroll
                for (int tm = 0; tm < 2; tm++) {
                    mma16(acc[tm][2 * p],     a[tm], bb0);
                    mma16(acc[tm][2 * p + 1], a[tm], bb1);
                }
            }
        }
    }

    const float QSC = 0.125f * 1.44269504088896f;
#pragma unroll
    for (int tm = 0; tm < 2; tm++) {
#pragma unroll
        for (int tn = 0; tn < 8; tn++) {
            const int cg = o0 + wn * 64 + tn * 8 + 2 * t4;
            const int h  = cg >> 6;
            const int d  = cg & 63;
            const int bh = b * NH + h;
            const float b0 = bias[cg], b1 = bias[cg + 1];
#pragma unroll
            for (int half = 0; half < 2; half++) {
                const int s = s0 + wm * 32 + tm * 16 + g + half * 8;
                float v0 = acc[tm][tn][half * 2 + 0] + b0;
                float v1 = acc[tm][tn][half * 2 + 1] + b1;
                if (which == 0) {
                    v0 *= QSC; v1 *= QSC;
                    *reinterpret_cast<unsigned*>(
                        &g_q16[((size_t)bh * SEQ + s) * HD + d]) = pack2(v0, v1);
                } else if (which == 1) {
                    *reinterpret_cast<unsigned*>(
                        &g_k16[((size_t)bh * SEQ + s) * HD + d]) = pack2(v0, v1);
                } else {
                    g_v16[((size_t)bh * HD + d) * SEQ + s]     = __float2half_rn(v0);
                    g_v16[((size_t)bh * HD + d + 1) * SEQ + s] = __float2half_rn(v1);
                }
            }
        }
    }
}

// ---------------------------------------------------------------------------
// Kernel 2: flash attention.  128-query tile, 8 warps x 16 rows, 64-key iters.
// ldmatrix B-frags; half2 exp; l via ones-column mma; skip-rescale guard.
// ---------------------------------------------------------------------------
extern __shared__ unsigned fa_sh[];

__global__ void __launch_bounds__(256, 2) flash_kernel()
{
    unsigned* Kb0 = fa_sh;               // [64][36]
    unsigned* Kb1 = Kb0 + 64 * 36;
    unsigned* Vb0 = Kb1 + 64 * 36;       // V[dd][j]
    unsigned* Vb1 = Vb0 + 64 * 36;

    const int t = threadIdx.x, lane = t & 31, wid = t >> 5;
    const int g = lane >> 2, t4 = lane & 3;
    const int bh = blockIdx.y, s0 = blockIdx.x * 128;
    const int b = bh >> 3, h = bh & 7;

    const unsigned* qU = reinterpret_cast<const unsigned*>(g_q16 + (size_t)bh * SEQ * HD);
    const __half*   kP = g_k16 + (size_t)bh * SEQ * HD;
    const __half*   vP = g_v16 + (size_t)bh * HD * SEQ;

#pragma unroll
    for (int u = 0; u < 2; u++) {
        int idx = t + u * 256;
        int r = idx >> 3, ch = idx & 7;
        cp16(&Kb0[r * 36 + ch * 4], kP + (size_t)r * HD + ch * 8);
        cp16(&Vb0[r * 36 + ch * 4], vP + (size_t)r * SEQ + ch * 8);
    }
    CP_COMMIT();

    const int row = wid * 16 + g;
    unsigned qf[4][4];
#pragma unroll
    for (int kc = 0; kc < 4; kc++) {
        qf[kc][0] = qU[(size_t)(s0 + row) * 32 + kc * 8 + t4];
        qf[kc][1] = qU[(size_t)(s0 + row + 8) * 32 + kc * 8 + t4];
        qf[kc][2] = qU[(size_t)(s0 + row) * 32 + kc * 8 + t4 + 4];
        qf[kc][3] = qU[(size_t)(s0 + row + 8) * 32 + kc * 8 + t4 + 4];
    }

    const int grp = lane >> 3, r8 = lane & 7;
    const int nrow = r8 + ((grp & 2) ? 8 : 0);
    const unsigned koff = (grp & 1) ? 16u : 0u;
    const unsigned sbase = (unsigned)__cvta_generic_to_shared(fa_sh);
    const unsigned BUF = 64 * 36 * 4;
    unsigned kA[2], vA[2];
    kA[0] = sbase + nrow * 144 + koff;
    kA[1] = kA[0] + BUF;
    vA[0] = kA[0] + 2 * BUF;
    vA[1] = kA[0] + 3 * BUF;

    unsigned bbl[2];
    bbl[0] = bbl[1] = (g == 0) ? 0x3C003C00u : 0u;

    CP_WAIT0();
    __syncthreads();

    float m0 = -1e30f, m1 = -1e30f;
    float oacc[8][4], lacc[4];
#pragma unroll
    for (int i = 0; i < 8; i++)
#pragma unroll
        for (int j = 0; j < 4; j++) oacc[i][j] = 0.f;
#pragma unroll
    for (int j = 0; j < 4; j++) lacc[j] = 0.f;

    for (int kt = 0; kt < 64; kt++) {
        const unsigned kBase = kA[kt & 1], vBase = vA[kt & 1];

        if (kt < 63) {
            unsigned* Kn = (kt & 1) ? Kb0 : Kb1;
            unsigned* Vn = (kt & 1) ? Vb0 : Vb1;
            const int koff2 = (kt + 1) * 64;
#pragma unroll
            for (int u = 0; u < 2; u++) {
                int idx = t + u * 256;
                int r = idx >> 3, ch = idx & 7;
                cp16(&Kn[r * 36 + ch * 4], kP + (size_t)(koff2 + r) * HD + ch * 8);
                cp16(&Vn[r * 36 + ch * 4], vP + (size_t)r * SEQ + koff2 + ch * 8);
            }
            CP_COMMIT();
        }

        // ---- S = Q K^T (log2 domain, pre-scaled) ----
        float s_f[8][4];
#pragma unroll
        for (int i = 0; i < 8; i++)
#pragma unroll
            for (int j = 0; j < 4; j++) s_f[i][j] = 0.f;

#pragma unroll
        for (int kc = 0; kc < 4; kc++) {
#pragma unroll
            for (int p = 0; p < 4; p++) {
                unsigned b0, b1, b2, b3;
                ldsm4(b0, b1, b2, b3, kBase + p * 2304 + kc * 32);
                unsigned bb0[2] = {b0, b1}, bb1[2] = {b2, b3};
                mma16(s_f[2 * p],     qf[kc], bb0);
                mma16(s_f[2 * p + 1], qf[kc], bb1);
            }
        }

        // ---- online softmax ----
        float mx0 = -1e30f, mx1 = -1e30f;
#pragma unroll
        for (int tn = 0; tn < 8; tn++) {
            mx0 = fmaxf(mx0, fmaxf(s_f[tn][0], s_f[tn][1]));
            mx1 = fmaxf(mx1, fmaxf(s_f[tn][2], s_f[tn][3]));
        }
        mx0 = fmaxf(mx0, __shfl_xor_sync(0xffffffffu, mx0, 1));
        mx0 = fmaxf(mx0, __shfl_xor_sync(0xffffffffu, mx0, 2));
        mx1 = fmaxf(mx1, __shfl_xor_sync(0xffffffffu, mx1, 1));
        mx1 = fmaxf(mx1, __shfl_xor_sync(0xffffffffu, mx1, 2));

        const bool up = (mx0 > m0) | (mx1 > m1);
        const float nm0 = fmaxf(m0, mx0), nm1 = fmaxf(m1, mx1);
        if (__any_sync(0xffffffffu, up)) {
            const float al0 = exp2f(m0 - nm0), al1 = exp2f(m1 - nm1);
#pragma unroll
            for (int tn = 0; tn < 8; tn++) {
                oacc[tn][0] *= al0; oacc[tn][1] *= al0;
                oacc[tn][2] *= al1; oacc[tn][3] *= al1;
            }
            lacc[0] *= al0; lacc[2] *= al1;
        }
        m0 = nm0; m1 = nm1;

        unsigned e01[8], e23[8];
#pragma unroll
        for (int tn = 0; tn < 8; tn++) {
            e01[tn] = ex2h2(s_f[tn][0] - nm0, s_f[tn][1] - nm0);
            e23[tn] = ex2h2(s_f[tn][2] - nm1, s_f[tn][3] - nm1);
        }

        // ---- O += P V ; l += P 1 ----
#pragma unroll
        for (int kc = 0; kc < 4; kc++) {
            unsigned a[4];
            a[0] = e01[2 * kc];     a[1] = e23[2 * kc];
            a[2] = e01[2 * kc + 1]; a[3] = e23[2 * kc + 1];
#pragma unroll
            for (int p = 0; p < 4; p++) {
                unsigned b0, b1, b2, b3;
                ldsm4(b0, b1, b2, b3, vBase + p * 2304 + kc * 32);
                unsigned bb0[2] = {b0, b1}, bb1[2] = {b2, b3};
                mma16(oacc[2 * p],     a, bb0);
                mma16(oacc[2 * p + 1], a, bb1);
            }
            mma16(lacc, a, bbl);
        }

        if (kt < 63) {
            CP_WAIT0();
            __syncthreads();
        }
    }

    const float l0 = __shfl_sync(0xffffffffu, lacc[0], lane & 28);
    const float l1 = __shfl_sync(0xffffffffu, lacc[2], lane & 28);
    const float r0 = 1.f / l0, r1 = 1.f / l1;
    const int srow = s0 + row;
#pragma unroll
    for (int tn = 0; tn < 8; tn++) {
        const int c = h * 64 + tn * 8 + 2 * t4;
        *reinterpret_cast<unsigned*>(&g_o16[((size_t)b * SEQ + srow) * CCH + c]) =
            pack2(oacc[tn][0] * r0, oacc[tn][1] * r0);
        *reinterpret_cast<unsigned*>(&g_o16[((size_t)b * SEQ + srow + 8) * CCH + c]) =
            pack2(oacc[tn][2] * r1, oacc[tn][3] * r1);
    }
}

// ---------------------------------------------------------------------------
// Kernel 3: out-projection.  Same pipelined structure as qkv.
// ---------------------------------------------------------------------------
__shared__ unsigned proj_sm[10240];

__global__ __launch_bounds__(256) void proj_kernel(
    const float* __restrict__ bp, float* __restrict__ out)
{
    const int t = threadIdx.x;
    const int lane = t & 31, wid = t >> 5;
    const int g = lane >> 2, t4 = lane & 3;
    const int wm = wid & 3, wn = wid >> 2;
    const int s0 = blockIdx.x * 128;
    const int o0 = blockIdx.y * 128;
    const int b  = blockIdx.z;

    const __half* aBase = g_o16 + (size_t)b * SEQ * CCH + (size_t)s0 * CCH;
    const __half* bBase = g_w16 + (size_t)3 * WSZ + (size_t)o0 * CCH;

    const int grp = lane >> 3, r8 = lane & 7;
    const unsigned sbase = (unsigned)__cvta_generic_to_shared(proj_sm);
    const int aRowAdd = ((grp & 1) << 3) + r8;
    const unsigned aKoff = (grp & 2) ? 16u : 0u;
    const int bRowAdd = ((grp & 2) << 2) + r8;
    const unsigned bKoff = (grp & 1) ? 16u : 0u;

    float acc[2][8][4];
#pragma unroll
    for (int i = 0; i < 2; i++)
#pragma unroll
        for (int j = 0; j < 8; j++)
#pragma unroll
            for (int q = 0; q < 4; q++) acc[i][j][q] = 0.f;

    stage_tile(proj_sm, proj_sm + 2560, aBase, bBase, t, 0);
    CP_COMMIT();

    for (int kt = 0; kt < 16; kt++) {
        CP_WAIT0();
        __syncthreads();
        const int buf = kt & 1;
        if (kt < 15) {
            const int nbuf = (kt + 1) & 1;
            stage_tile(proj_sm + nbuf * 5120, proj_sm + nbuf * 5120 + 2560,
                       aBase, bBase, t, (kt + 1) * 32);
            CP_COMMIT();
        }
        const unsigned aB = sbase + (buf * 5120) * 4;
        const unsigned bB = sbase + (buf * 5120 + 2560) * 4;

#pragma unroll
        for (int kc = 0; kc < 2; kc++) {
            unsigned a[2][4];
#pragma unroll
            for (int tm = 0; tm < 2; tm++) {
                const int mrow = wm * 32 + tm * 16;
                ldsm4(a[tm][0], a[tm][1], a[tm][2], a[tm][3],
                      aB + (unsigned)(mrow + aRowAdd) * 80 + aKoff + kc * 32);
            }
#pragma unroll
            for (int p = 0; p < 4; p++) {
                unsigned b0, b1, b2, b3;
                const int nrow = wn * 64 + p * 16;
                ldsm4(b0, b1, b2, b3,
                      bB + (unsigned)(nrow + bRowAdd) * 80 + bKoff + kc * 32);
                unsigned bb0[2] = {b0, b1}, bb1[2] = {b2, b3};
#pragma unroll
                for (int tm = 0; tm < 2; tm++) {
                    mma16(acc[tm][2 * p],     a[tm], bb0);
                    mma16(acc[tm][2 * p + 1], a[tm], bb1);
                }
            }
        }
    }

#pragma unroll
    for (int tm = 0; tm < 2; tm++) {
#pragma unroll
        for (int tn = 0; tn < 8; tn++) {
            const int col0 = o0 + wn * 64 + tn * 8 + 2 * t4;
            const float b0 = bp[col0], b1 = bp[col0 + 1];
#pragma unroll
            for (int half = 0; half < 2; half++) {
                const int s = s0 + wm * 32 + tm * 16 + g + half * 8;
                out[((size_t)b * CCH + col0) * SEQ + s]     = acc[tm][tn][half * 2 + 0] + b0;
                out[((size_t)b * CCH + col0 + 1) * SEQ + s] = acc[tm][tn][half * 2 + 1] + b1;
            }
        }
    }
}

// ---------------------------------------------------------------------------
extern "C" void kernel_launch(void* const* d_in, const int* in_sizes, int n_in,
                              void* d_out, int out_size)
{
    const float* x  = (const float*)d_in[0];
    const float* Wq = (const float*)d_in[1];
    const float* bq = (const float*)d_in[2];
    const float* Wk = (const float*)d_in[3];
    const float* bk = (const float*)d_in[4];
    const float* Wv = (const float*)d_in[5];
    const float* bv = (const float*)d_in[6];
    const float* Wp = (const float*)d_in[7];
    const float* bp = (const float*)d_in[8];
    float* out = (float*)d_out;

    const int FA_SMEM = 4 * 64 * 36 * 4;  // 36864 B
    cudaFuncSetAttribute(flash_kernel,
                         cudaFuncAttributeMaxDynamicSharedMemorySize, FA_SMEM);

    transpose_kernel<<<dim3(SEQ / 32, CCH / 32, BATCH), 256>>>(x);
    wconv_kernel<<<1024, 256>>>(Wq, Wk, Wv, Wp);
    qkv_kernel<<<dim3(SEQ / 128, CCH / 128, 3 * BATCH), 256>>>(bq, bk, bv);
    flash_kernel<<<dim3(SEQ / 128, BH), 256, FA_SMEM>>>();
    proj_kernel<<<dim3(SEQ / 128, CCH / 128, BATCH), 256>>>(bp, out);
}